// round 1
// baseline (speedup 1.0000x reference)
#include <cuda_runtime.h>
#include <math_constants.h>

#define NBINS_ABS 1024
#define ABS_OFF   512
#define NTAB      195   // g length = hist_add pairs used by pass 3
#define NHA       196   // hist_add length

__device__ unsigned int g_minbits;
__device__ unsigned int g_hist[NBINS_ABS];
__device__ double       g_acc;
__device__ float2       g_table[NTAB];
__device__ float        g_vminnew;

static __device__ __forceinline__ unsigned int fkey(float f) {
    unsigned int b = __float_as_uint(f);
    return b ^ ((unsigned int)((int)b >> 31) | 0x80000000u);
}

// ---------------------------------------------------------------- init
__global__ void k_init() {
    int t = threadIdx.x;
    if (t < NBINS_ABS) g_hist[t] = 0u;
    if (t == 0) { g_minbits = 0xFFFFFFFFu; g_acc = 0.0; }
}

// ---------------------------------------------------------------- pass 1: min + abs histogram
#define K1_WARPS 8
__global__ void __launch_bounds__(256) k_hist(const float* __restrict__ xp, int n) {
    __shared__ unsigned int sh[K1_WARPS][NBINS_ABS];   // 32 KB: per-warp private hist
    __shared__ float s_wmin[K1_WARPS];
    const int tid  = threadIdx.x;
    const int lane = tid & 31;
    const int wid  = tid >> 5;

    for (int i = tid; i < K1_WARPS * NBINS_ABS; i += blockDim.x)
        ((unsigned int*)sh)[i] = 0u;
    __syncthreads();

    unsigned int* h = sh[wid];
    float lmin = CUDART_INF_F;

    const int n4 = n >> 2;
    const float4* x4 = (const float4*)xp;
    const int stride = gridDim.x * blockDim.x;

    for (int i = blockIdx.x * blockDim.x + tid; i < n4; i += stride) {
        float4 v = x4[i];
        lmin = fminf(lmin, fminf(fminf(v.x, v.y), fminf(v.z, v.w)));
        unsigned int amask = __activemask();
        {
            int b = min(NBINS_ABS - 1, max(0, __float2int_rd(v.x * 5.0f) + ABS_OFF));
            unsigned int m = __match_any_sync(amask, b);
            if (lane == __ffs(m) - 1) h[b] += __popc(m);
        }
        {
            int b = min(NBINS_ABS - 1, max(0, __float2int_rd(v.y * 5.0f) + ABS_OFF));
            unsigned int m = __match_any_sync(amask, b);
            if (lane == __ffs(m) - 1) h[b] += __popc(m);
        }
        {
            int b = min(NBINS_ABS - 1, max(0, __float2int_rd(v.z * 5.0f) + ABS_OFF));
            unsigned int m = __match_any_sync(amask, b);
            if (lane == __ffs(m) - 1) h[b] += __popc(m);
        }
        {
            int b = min(NBINS_ABS - 1, max(0, __float2int_rd(v.w * 5.0f) + ABS_OFF));
            unsigned int m = __match_any_sync(amask, b);
            if (lane == __ffs(m) - 1) h[b] += __popc(m);
        }
    }

    // ragged tail (n % 4), handled by block 0 directly in global
    if (blockIdx.x == 0 && tid < (n & 3)) {
        float f = xp[(n & ~3) + tid];
        int b = min(NBINS_ABS - 1, max(0, __float2int_rd(f * 5.0f) + ABS_OFF));
        atomicAdd(&g_hist[b], 1u);
        atomicMin(&g_minbits, fkey(f));
    }

    // warp min -> block min -> global
    #pragma unroll
    for (int o = 16; o; o >>= 1)
        lmin = fminf(lmin, __shfl_xor_sync(0xFFFFFFFFu, lmin, o));
    if (lane == 0) s_wmin[wid] = lmin;
    __syncthreads();
    if (wid == 0) {
        float a = (lane < K1_WARPS) ? s_wmin[lane] : CUDART_INF_F;
        #pragma unroll
        for (int o = 16; o; o >>= 1)
            a = fminf(a, __shfl_xor_sync(0xFFFFFFFFu, a, o));
        if (lane == 0) atomicMin(&g_minbits, fkey(a));
    }

    // merge per-warp hists -> global
    for (int i = tid; i < NBINS_ABS; i += blockDim.x) {
        unsigned int s = 0;
        #pragma unroll
        for (int w = 0; w < K1_WARPS; w++) s += sh[w][i];
        if (s) atomicAdd(&g_hist[i], s);
    }
}

// ---------------------------------------------------------------- pass 2: build tables (1 block, 1024 threads)
__global__ void __launch_bounds__(1024) k_table(double inv_n) {
    __shared__ unsigned int s_cum[NBINS_ABS];
    __shared__ unsigned int s_ws[32];
    __shared__ float s_ha[NHA];
    const int tid  = threadIdx.x;
    const int lane = tid & 31;
    const int wid  = tid >> 5;

    unsigned int v = g_hist[tid];
    unsigned int x = v;
    #pragma unroll
    for (int o = 1; o < 32; o <<= 1) {
        unsigned int y = __shfl_up_sync(0xFFFFFFFFu, x, o);
        if (lane >= o) x += y;
    }
    if (lane == 31) s_ws[wid] = x;
    __syncthreads();
    if (wid == 0) {
        unsigned int w = s_ws[lane];
        unsigned int xx = w;
        #pragma unroll
        for (int o = 1; o < 32; o <<= 1) {
            unsigned int y = __shfl_up_sync(0xFFFFFFFFu, xx, o);
            if (lane >= o) xx += y;
        }
        s_ws[lane] = xx - w;   // exclusive warp offsets
    }
    __syncthreads();
    s_cum[tid] = x + s_ws[wid];   // inclusive abs cumsum
    __syncthreads();

    const unsigned int total = s_cum[NBINS_ABS - 1];
    unsigned int u = g_minbits;
    float fmn = (u & 0x80000000u) ? __uint_as_float(u ^ 0x80000000u)
                                  : __uint_as_float(~u);
    float vmin = floorf(fmn) - 1.0f;
    int base = 5 * (int)vmin + ABS_OFF;

    if (tid < NHA) {   // hist_add[j] = (c[j+5]-c[j])/n with edge clipping
        int j = tid;
        double lo, hi;
        if (j == 0) lo = 0.0;
        else {
            int k = base + j - 1;
            lo = (k < 0) ? 0.0 : (double)((k >= NBINS_ABS) ? total : s_cum[k]);
        }
        if (j >= NHA - 1) hi = (double)total;   // c[200] = total (top clip)
        else {
            int k = base + j + 4;
            hi = (k < 0) ? 0.0 : (double)((k >= NBINS_ABS) ? total : s_cum[k]);
        }
        s_ha[j] = (float)((hi - lo) * inv_n);
    }
    __syncthreads();
    if (tid < NTAB) {
        float gg = (s_ha[tid + 1] - s_ha[tid]) * 5.0f;
        g_table[tid] = make_float2(gg, s_ha[tid]);
    }
    if (tid == 0) g_vminnew = vmin + 0.5f;
}

// ---------------------------------------------------------------- pass 3: loss
static __device__ __forceinline__ float nloss_of(float xv, float vmn, const float2* tab) {
    float t = (xv - vmn) * 5.0f;
    int i = __float2int_rd(t);
    i = max(0, min(i, NTAB - 1));
    float2 gh = tab[i];
    float left = fmaf((float)i, 0.2f, vmn);
    return fmaf(xv - left, gh.x, gh.y) + 1e-8f;
}

static __device__ __forceinline__ void prod4(const float4& v, float vmn, const float2* tab,
                                             int& e, float& m) {
    float p = nloss_of(v.x, vmn, tab) * nloss_of(v.y, vmn, tab)
            * nloss_of(v.z, vmn, tab) * nloss_of(v.w, vmn, tab);
    unsigned int ub = __float_as_uint(p);
    e = (int)(ub >> 23) - 127;
    m = __uint_as_float((ub & 0x007FFFFFu) | 0x3F800000u);
}

__global__ void __launch_bounds__(256) k_loss(const float* __restrict__ xp, int n) {
    __shared__ float2 tab[NTAB];
    for (int i = threadIdx.x; i < NTAB; i += blockDim.x) tab[i] = g_table[i];
    __syncthreads();
    const float vmn = g_vminnew;

    const int n4 = n >> 2;
    const float4* x4 = (const float4*)xp;
    const int tid = blockIdx.x * blockDim.x + threadIdx.x;
    const int stride = gridDim.x * blockDim.x;

    float acc = 0.0f;
    for (int i = tid; i < n4; i += 2 * stride) {
        float4 a = x4[i];
        int ea; float ma;
        prod4(a, vmn, tab, ea, ma);
        int j = i + stride;
        if (j < n4) {
            float4 b = x4[j];
            int eb; float mb;
            prod4(b, vmn, tab, eb, mb);
            acc += (float)(ea + eb) + __log2f(ma * mb);
        } else {
            acc += (float)ea + __log2f(ma);
        }
    }
    // ragged tail
    if (blockIdx.x == 0 && threadIdx.x < (n & 3)) {
        float f = xp[(n & ~3) + threadIdx.x];
        acc += __log2f(nloss_of(f, vmn, tab));
    }

    // reduce: warp -> block -> global double atomic
    #pragma unroll
    for (int o = 16; o; o >>= 1) acc += __shfl_xor_sync(0xFFFFFFFFu, acc, o);
    __shared__ float ws[8];
    if ((threadIdx.x & 31) == 0) ws[threadIdx.x >> 5] = acc;
    __syncthreads();
    if (threadIdx.x < 32) {
        float a = (threadIdx.x < (blockDim.x >> 5)) ? ws[threadIdx.x] : 0.0f;
        #pragma unroll
        for (int o = 4; o; o >>= 1) a += __shfl_xor_sync(0xFFFFFFFFu, a, o);
        if (threadIdx.x == 0) atomicAdd(&g_acc, (double)a);
    }
}

// ---------------------------------------------------------------- finalize
__global__ void k_final(float* out, double inv_n) {
    // rloss/n = -(sum log2 nloss)/n
    out[0] = (float)(-g_acc * inv_n);
}

// ---------------------------------------------------------------- launch
extern "C" void kernel_launch(void* const* d_in, const int* in_sizes, int n_in,
                              void* d_out, int out_size) {
    const float* x = (const float*)d_in[0];
    const int n = in_sizes[0];
    const double inv_n = 1.0 / (double)n;

    k_init<<<1, 1024>>>();
    k_hist<<<592, 256>>>(x, n);
    k_table<<<1, 1024>>>(inv_n);
    k_loss<<<1184, 256>>>(x, n);
    k_final<<<1, 1>>>((float*)d_out, inv_n);
}

// round 2
// speedup vs baseline: 1.6302x; 1.6302x over previous
#include <cuda_runtime.h>
#include <math_constants.h>

#define NBINS_ABS 1024
#define ABS_OFF   512
#define NTAB      195   // g length = table entries used by pass 3
#define NHA       196   // hist_add length
#define LBINS     64    // local per-thread histogram bins: floor(5x) in [-32,31]
#define LBASE     (ABS_OFF - 32)   // abs bin of local bin 0

__device__ unsigned int g_minbits;
__device__ unsigned int g_hist[NBINS_ABS];
__device__ double       g_acc;
__device__ float2       g_table[NTAB];   // (ha[i+1]-ha[i], ha[i]+1e-8)
__device__ float        g_nvmn5;         // -(vmin+0.5)*5

static __device__ __forceinline__ unsigned int fkey(float f) {
    unsigned int b = __float_as_uint(f);
    return b ^ ((unsigned int)((int)b >> 31) | 0x80000000u);
}

// ---------------------------------------------------------------- init
__global__ void k_init() {
    int t = threadIdx.x;
    if (t < NBINS_ABS) g_hist[t] = 0u;
    if (t == 0) { g_minbits = 0xFFFFFFFFu; g_acc = 0.0; }
}

// ---------------------------------------------------------------- pass 1: min + histogram
// Per-THREAD private u16 counters (2 packed per u32), conflict-free layout.
static __device__ __forceinline__ void hbin(float f, unsigned int* sh, int tid) {
    int b = __float2int_rd(f * 5.0f);
    unsigned int l = (unsigned int)(b + 32);
    if (l < LBINS) {
        int w = (int)(l >> 1) * 256 + tid;
        sh[w] += (l & 1u) ? 65536u : 1u;
    } else {
        atomicAdd(&g_hist[min(NBINS_ABS - 1, max(0, b + ABS_OFF))], 1u);
    }
}

__global__ void __launch_bounds__(256) k_hist(const float* __restrict__ xp, int n) {
    __shared__ unsigned int sh[(LBINS / 2) * 256];   // 32 KB
    __shared__ float s_wmin[8];
    const int tid  = threadIdx.x;
    const int lane = tid & 31;
    const int wid  = tid >> 5;

    #pragma unroll
    for (int i = 0; i < LBINS / 2; i++) sh[i * 256 + tid] = 0u;
    __syncthreads();

    float lmin = CUDART_INF_F;
    const int n4 = n >> 2;
    const float4* x4 = (const float4*)xp;
    const int stride = gridDim.x * blockDim.x;

    for (int i = blockIdx.x * blockDim.x + tid; i < n4; i += stride) {
        float4 v = x4[i];
        lmin = fminf(lmin, fminf(fminf(v.x, v.y), fminf(v.z, v.w)));
        hbin(v.x, sh, tid);
        hbin(v.y, sh, tid);
        hbin(v.z, sh, tid);
        hbin(v.w, sh, tid);
    }

    // ragged tail (n % 4): block 0 via global atomics
    if (blockIdx.x == 0 && tid < (n & 3)) {
        float f = xp[(n & ~3) + tid];
        atomicAdd(&g_hist[min(NBINS_ABS - 1, max(0, __float2int_rd(f * 5.0f) + ABS_OFF))], 1u);
        atomicMin(&g_minbits, fkey(f));
    }

    // warp min -> block min -> global
    #pragma unroll
    for (int o = 16; o; o >>= 1)
        lmin = fminf(lmin, __shfl_xor_sync(0xFFFFFFFFu, lmin, o));
    if (lane == 0) s_wmin[wid] = lmin;
    __syncthreads();
    if (wid == 0) {
        float a = (lane < 8) ? s_wmin[lane] : CUDART_INF_F;
        #pragma unroll
        for (int o = 16; o; o >>= 1)
            a = fminf(a, __shfl_xor_sync(0xFFFFFFFFu, a, o));
        if (lane == 0) atomicMin(&g_minbits, fkey(a));
    }

    // merge: each warp reduces words w = wid, wid+8, ... (bin pair 2w, 2w+1)
    for (int w = wid; w < LBINS / 2; w += 8) {
        unsigned int s = 0;
        #pragma unroll
        for (int k = 0; k < 8; k++) s += sh[w * 256 + lane + 32 * k];  // fields <= 8*221, no carry
        unsigned int slo = s & 0xFFFFu, shi = s >> 16;
        #pragma unroll
        for (int o = 16; o; o >>= 1) {
            slo += __shfl_xor_sync(0xFFFFFFFFu, slo, o);
            shi += __shfl_xor_sync(0xFFFFFFFFu, shi, o);
        }
        if (lane == 0) {
            if (slo) atomicAdd(&g_hist[LBASE + 2 * w],     slo);
            if (shi) atomicAdd(&g_hist[LBASE + 2 * w + 1], shi);
        }
    }
}

// ---------------------------------------------------------------- pass 2: build tables (1 block, 1024 threads)
__global__ void __launch_bounds__(1024) k_table(double inv_n) {
    __shared__ unsigned int s_cum[NBINS_ABS];
    __shared__ unsigned int s_ws[32];
    __shared__ float s_ha[NHA];
    const int tid  = threadIdx.x;
    const int lane = tid & 31;
    const int wid  = tid >> 5;

    unsigned int v = g_hist[tid];
    unsigned int x = v;
    #pragma unroll
    for (int o = 1; o < 32; o <<= 1) {
        unsigned int y = __shfl_up_sync(0xFFFFFFFFu, x, o);
        if (lane >= o) x += y;
    }
    if (lane == 31) s_ws[wid] = x;
    __syncthreads();
    if (wid == 0) {
        unsigned int w = s_ws[lane];
        unsigned int xx = w;
        #pragma unroll
        for (int o = 1; o < 32; o <<= 1) {
            unsigned int y = __shfl_up_sync(0xFFFFFFFFu, xx, o);
            if (lane >= o) xx += y;
        }
        s_ws[lane] = xx - w;   // exclusive warp offsets
    }
    __syncthreads();
    s_cum[tid] = x + s_ws[wid];   // inclusive abs cumsum
    __syncthreads();

    const unsigned int total = s_cum[NBINS_ABS - 1];
    unsigned int u = g_minbits;
    float fmn = (u & 0x80000000u) ? __uint_as_float(u ^ 0x80000000u)
                                  : __uint_as_float(~u);
    float vmin = floorf(fmn) - 1.0f;
    int base = 5 * (int)vmin + ABS_OFF;

    if (tid < NHA) {   // hist_add[j] = (c[j+5]-c[j])/n with edge clipping
        int j = tid;
        double lo, hi;
        if (j == 0) lo = 0.0;
        else {
            int k = base + j - 1;
            lo = (k < 0) ? 0.0 : (double)((k >= NBINS_ABS) ? total : s_cum[k]);
        }
        if (j >= NHA - 1) hi = (double)total;
        else {
            int k = base + j + 4;
            hi = (k < 0) ? 0.0 : (double)((k >= NBINS_ABS) ? total : s_cum[k]);
        }
        s_ha[j] = (float)((hi - lo) * inv_n);
    }
    __syncthreads();
    if (tid < NTAB) {
        // pre-scaled: nloss = frac * (ha[i+1]-ha[i]) + (ha[i]+1e-8), frac = t - i
        g_table[tid] = make_float2(s_ha[tid + 1] - s_ha[tid], s_ha[tid] + 1e-8f);
    }
    if (tid == 0) g_nvmn5 = -((vmin + 0.5f) * 5.0f);
}

// ---------------------------------------------------------------- pass 3: loss
static __device__ __forceinline__ float nloss_of(float xv, float nvmn5,
                                                 const float2* tab, int lsel) {
    float t = fmaf(xv, 5.0f, nvmn5);     // (x - vmn_new) * 5, >= 2.5 since x >= min
    int i = __float2int_rd(t);
    i = min(i, NTAB - 1);
    float2 gh = tab[(i << 2) | lsel];    // 4x lane-replicated table
    return fmaf(t - (float)i, gh.x, gh.y);
}

static __device__ __forceinline__ void prod4(const float4& v, float nvmn5,
                                             const float2* tab, int lsel,
                                             int& e, float& m) {
    float p = nloss_of(v.x, nvmn5, tab, lsel) * nloss_of(v.y, nvmn5, tab, lsel)
            * nloss_of(v.z, nvmn5, tab, lsel) * nloss_of(v.w, nvmn5, tab, lsel);
    unsigned int ub = __float_as_uint(p);
    e = (int)(ub >> 23) - 127;
    m = __uint_as_float((ub & 0x007FFFFFu) | 0x3F800000u);
}

__global__ void __launch_bounds__(256) k_loss(const float* __restrict__ xp, int n) {
    __shared__ float2 tab[NTAB * 4];
    for (int i = threadIdx.x; i < NTAB; i += blockDim.x) {
        float2 t = g_table[i];
        tab[i * 4 + 0] = t; tab[i * 4 + 1] = t;
        tab[i * 4 + 2] = t; tab[i * 4 + 3] = t;
    }
    __syncthreads();
    const float nvmn5 = g_nvmn5;
    const int lsel = threadIdx.x & 3;

    const int n4 = n >> 2;
    const float4* x4 = (const float4*)xp;
    const int tid = blockIdx.x * blockDim.x + threadIdx.x;
    const int stride = gridDim.x * blockDim.x;

    float acc = 0.0f;
    for (int i = tid; i < n4; i += 2 * stride) {
        float4 a = x4[i];
        int ea; float ma;
        prod4(a, nvmn5, tab, lsel, ea, ma);
        int j = i + stride;
        if (j < n4) {
            float4 b = x4[j];
            int eb; float mb;
            prod4(b, nvmn5, tab, lsel, eb, mb);
            acc += (float)(ea + eb) + __log2f(ma * mb);
        } else {
            acc += (float)ea + __log2f(ma);
        }
    }
    // ragged tail
    if (blockIdx.x == 0 && threadIdx.x < (n & 3)) {
        float f = xp[(n & ~3) + threadIdx.x];
        acc += __log2f(nloss_of(f, nvmn5, tab, lsel));
    }

    // reduce: warp -> block -> global double atomic
    #pragma unroll
    for (int o = 16; o; o >>= 1) acc += __shfl_xor_sync(0xFFFFFFFFu, acc, o);
    __shared__ float ws[8];
    if ((threadIdx.x & 31) == 0) ws[threadIdx.x >> 5] = acc;
    __syncthreads();
    if (threadIdx.x < 32) {
        float a = (threadIdx.x < (blockDim.x >> 5)) ? ws[threadIdx.x] : 0.0f;
        #pragma unroll
        for (int o = 4; o; o >>= 1) a += __shfl_xor_sync(0xFFFFFFFFu, a, o);
        if (threadIdx.x == 0) atomicAdd(&g_acc, (double)a);
    }
}

// ---------------------------------------------------------------- finalize
__global__ void k_final(float* out, double inv_n) {
    out[0] = (float)(-g_acc * inv_n);
}

// ---------------------------------------------------------------- launch
extern "C" void kernel_launch(void* const* d_in, const int* in_sizes, int n_in,
                              void* d_out, int out_size) {
    const float* x = (const float*)d_in[0];
    const int n = in_sizes[0];
    const double inv_n = 1.0 / (double)n;

    k_init<<<1, 1024>>>();
    k_hist<<<1036, 256>>>(x, n);
    k_table<<<1, 1024>>>(inv_n);
    k_loss<<<1184, 256>>>(x, n);
    k_final<<<1, 1>>>((float*)d_out, inv_n);
}

// round 3
// speedup vs baseline: 1.9003x; 1.1657x over previous
#include <cuda_runtime.h>
#include <math_constants.h>

#define NBINS_ABS 1024
#define ABS_OFF   512
#define NTAB      195
#define NHA       196
#define LBINS     64                 // local bins: floor(5x) in [-32,31]
#define LBASE     (ABS_OFF - 32)

__device__ unsigned int g_hist[NBINS_ABS];
__device__ int          g_minneg;    // max over outliers of (4096 - floor(5x)); 0 = none
__device__ double       g_acc;
__device__ float2       g_table[NTAB];   // (A, B): nloss = t*A + B
__device__ float        g_nvmn5;         // -(vmin+0.5)*5

// ---------------------------------------------------------------- pass 1: histogram (min derived from hist)
static __device__ __forceinline__ void hbin(float f, unsigned char* sh8, int tid) {
    int b = __float2int_rd(f * 5.0f);
    unsigned int l = (unsigned int)(b + 32);
    if (l < LBINS) {
        sh8[(int)l * 256 + tid]++;
    } else {
        atomicAdd(&g_hist[min(NBINS_ABS - 1, max(0, b + ABS_OFF))], 1u);
        atomicMax(&g_minneg, 4096 - b);   // exact low-side position (high-side harmless)
    }
}

__global__ void __launch_bounds__(256) k_hist(const float* __restrict__ xp, int n) {
    __shared__ unsigned char sh8[LBINS * 256];   // 16 KB, per-thread u8 counters
    const int tid  = threadIdx.x;
    const int lane = tid & 31;
    const int wid  = tid >> 5;

    #pragma unroll
    for (int i = 0; i < LBINS / 4; i++)
        ((unsigned int*)sh8)[i * 256 + tid] = 0u;
    __syncthreads();

    const int n4 = n >> 2;
    const float4* x4 = (const float4*)xp;
    const int stride = gridDim.x * blockDim.x;

    for (int i = blockIdx.x * blockDim.x + tid; i < n4; i += 2 * stride) {
        float4 a = x4[i];
        int j = i + stride;
        bool hasb = (j < n4);
        float4 b;
        if (hasb) b = x4[j];
        hbin(a.x, sh8, tid); hbin(a.y, sh8, tid);
        hbin(a.z, sh8, tid); hbin(a.w, sh8, tid);
        if (hasb) {
            hbin(b.x, sh8, tid); hbin(b.y, sh8, tid);
            hbin(b.z, sh8, tid); hbin(b.w, sh8, tid);
        }
    }

    // ragged tail (n % 4): block 0 via global atomics
    if (blockIdx.x == 0 && tid < (n & 3)) {
        float f = xp[(n & ~3) + tid];
        int b = __float2int_rd(f * 5.0f);
        atomicAdd(&g_hist[min(NBINS_ABS - 1, max(0, b + ABS_OFF))], 1u);
        atomicMax(&g_minneg, 4096 - b);
    }
    __syncthreads();

    // merge: warp w handles bin rows w, w+8, ...; dp4a byte-sum
    for (int l = wid; l < LBINS; l += 8) {
        const unsigned int* row = (const unsigned int*)(sh8 + l * 256);
        unsigned int s = __dp4a(row[lane], 0x01010101u, 0u)
                       + __dp4a(row[lane + 32], 0x01010101u, 0u);
        #pragma unroll
        for (int o = 16; o; o >>= 1) s += __shfl_xor_sync(0xFFFFFFFFu, s, o);
        if (lane == 0 && s) atomicAdd(&g_hist[LBASE + l], s);
    }
}

// ---------------------------------------------------------------- pass 2: tables (1 block, 1024 threads)
__global__ void __launch_bounds__(1024) k_table(double inv_n) {
    __shared__ unsigned int s_cum[NBINS_ABS];
    __shared__ unsigned int s_ws[32];
    __shared__ float s_ha[NHA];
    __shared__ int s_b0;
    const int tid  = threadIdx.x;
    const int lane = tid & 31;
    const int wid  = tid >> 5;

    unsigned int v = g_hist[tid];
    g_hist[tid] = 0u;                       // reset for next replay
    if (tid == 0) {
        int mn = atomicExch(&g_minneg, 0);  // consume + reset
        s_b0 = mn ? (4096 - mn) + ABS_OFF : 0x7FFFFFFF;
    }
    __syncthreads();
    if (v) atomicMin(&s_b0, tid);           // lowest non-empty abs bin

    // inclusive scan of v over 1024 bins
    unsigned int x = v;
    #pragma unroll
    for (int o = 1; o < 32; o <<= 1) {
        unsigned int y = __shfl_up_sync(0xFFFFFFFFu, x, o);
        if (lane >= o) x += y;
    }
    if (lane == 31) s_ws[wid] = x;
    __syncthreads();
    if (wid == 0) {
        unsigned int w = s_ws[lane];
        unsigned int xx = w;
        #pragma unroll
        for (int o = 1; o < 32; o <<= 1) {
            unsigned int y = __shfl_up_sync(0xFFFFFFFFu, xx, o);
            if (lane >= o) xx += y;
        }
        s_ws[lane] = xx - w;
    }
    __syncthreads();
    s_cum[tid] = x + s_ws[wid];
    __syncthreads();

    const unsigned int total = s_cum[NBINS_ABS - 1];
    // vmin = floor(xmin) - 1, from lowest bin: floor(x) = floordiv(floor(5x), 5)
    int b0rel = s_b0 - ABS_OFF;             // floor(5 * xmin)
    int fd = (b0rel >= 0) ? (b0rel / 5) : -((-b0rel + 4) / 5);
    int vmin_i = fd - 1;
    int base = 5 * vmin_i + ABS_OFF;

    if (tid < NHA) {
        int j = tid;
        double lo, hi;
        if (j == 0) lo = 0.0;
        else {
            int k = base + j - 1;
            lo = (k < 0) ? 0.0 : (double)((k >= NBINS_ABS) ? total : s_cum[k]);
        }
        if (j >= NHA - 1) hi = (double)total;
        else {
            int k = base + j + 4;
            hi = (k < 0) ? 0.0 : (double)((k >= NBINS_ABS) ? total : s_cum[k]);
        }
        s_ha[j] = (float)((hi - lo) * inv_n);
    }
    __syncthreads();
    if (tid < NTAB) {
        float A = s_ha[tid + 1] - s_ha[tid];
        float B = (float)((double)s_ha[tid] + 1e-8 - (double)tid * (double)A);
        g_table[tid] = make_float2(A, B);
    }
    if (tid == 0) g_nvmn5 = -(((float)vmin_i + 0.5f) * 5.0f);
}

// ---------------------------------------------------------------- pass 3: loss
static __device__ __forceinline__ float nloss_of(float xv, float nvmn5, const float2* tab) {
    float t = fmaf(xv, 5.0f, nvmn5);     // >= 2.5 since x >= min
    int i = min(__float2int_rd(t), NTAB - 1);
    float2 ab = tab[i];
    return fmaf(t, ab.x, ab.y);          // handles clamp-extrapolation exactly
}

static __device__ __forceinline__ void prod4(const float4& v, float nvmn5,
                                             const float2* tab, int& e, float& m) {
    float p = nloss_of(v.x, nvmn5, tab) * nloss_of(v.y, nvmn5, tab)
            * nloss_of(v.z, nvmn5, tab) * nloss_of(v.w, nvmn5, tab);
    unsigned int ub = __float_as_uint(p);
    e = (int)(ub >> 23) - 127;
    m = __uint_as_float((ub & 0x007FFFFFu) | 0x3F800000u);
}

__global__ void __launch_bounds__(256) k_loss(const float* __restrict__ xp, int n) {
    __shared__ float2 tab[NTAB];
    for (int i = threadIdx.x; i < NTAB; i += blockDim.x) tab[i] = g_table[i];
    __syncthreads();
    const float nvmn5 = g_nvmn5;

    const int n4 = n >> 2;
    const float4* x4 = (const float4*)xp;
    const int tid = blockIdx.x * blockDim.x + threadIdx.x;
    const int stride = gridDim.x * blockDim.x;

    float acc = 0.0f;
    // REVERSE traversal: read the addresses k_hist most recently pulled into L2.
    for (int i = tid; i < n4; i += 2 * stride) {
        float4 a = x4[n4 - 1 - i];
        int ea; float ma;
        prod4(a, nvmn5, tab, ea, ma);
        int j = i + stride;
        if (j < n4) {
            float4 b = x4[n4 - 1 - j];
            int eb; float mb;
            prod4(b, nvmn5, tab, eb, mb);
            acc += (float)(ea + eb) + __log2f(ma * mb);
        } else {
            acc += (float)ea + __log2f(ma);
        }
    }
    if (blockIdx.x == 0 && threadIdx.x < (n & 3)) {
        float f = xp[(n & ~3) + threadIdx.x];
        acc += __log2f(nloss_of(f, nvmn5, tab));
    }

    #pragma unroll
    for (int o = 16; o; o >>= 1) acc += __shfl_xor_sync(0xFFFFFFFFu, acc, o);
    __shared__ float ws[8];
    if ((threadIdx.x & 31) == 0) ws[threadIdx.x >> 5] = acc;
    __syncthreads();
    if (threadIdx.x < 32) {
        float a = (threadIdx.x < (blockDim.x >> 5)) ? ws[threadIdx.x] : 0.0f;
        #pragma unroll
        for (int o = 4; o; o >>= 1) a += __shfl_xor_sync(0xFFFFFFFFu, a, o);
        if (threadIdx.x == 0) atomicAdd(&g_acc, (double)a);
    }
}

// ---------------------------------------------------------------- finalize (consume + reset acc)
__global__ void k_final(float* out, double inv_n) {
    double a = g_acc;
    g_acc = 0.0;
    out[0] = (float)(-a * inv_n);
}

// ---------------------------------------------------------------- launch
extern "C" void kernel_launch(void* const* d_in, const int* in_sizes, int n_in,
                              void* d_out, int out_size) {
    const float* x = (const float*)d_in[0];
    const int n = in_sizes[0];
    const double inv_n = 1.0 / (double)n;

    k_hist<<<1184, 256>>>(x, n);
    k_table<<<1, 1024>>>(inv_n);
    k_loss<<<1184, 256>>>(x, n);
    k_final<<<1, 1>>>((float*)d_out, inv_n);
}

// round 4
// speedup vs baseline: 1.9920x; 1.0483x over previous
#include <cuda_runtime.h>
#include <math_constants.h>

#define NBINS_ABS 1024
#define ABS_OFF   512
#define NTAB      195
#define NHA       196
#define LBINS     64                 // local bins: floor(5x) in [-32,31]
#define LBASE     (ABS_OFF - 32)
#define MAGIC_F   8388640.0f         // 2^23 + 32
#define MAGIC_U   0x4B000000u        // bits(2^23)
#define GRID_N    1184

__device__ unsigned int g_hist[NBINS_ABS];
__device__ int          g_minneg;    // max over outliers of (4096 - floor(5x)); 0 = none
__device__ double       g_acc;
__device__ float2       g_table[NTAB];   // (A, B): nloss = t*A + B
__device__ float        g_nvmn5;         // -(vmin+0.5)*5
__device__ unsigned int g_tick1;
__device__ unsigned int g_tick2;

// ---------------------------------------------------------------- slow path for out-of-local-range values
static __device__ __noinline__ void hbin_slow(float f) {
    int b = __float2int_rd(f * 5.0f);
    atomicAdd(&g_hist[min(NBINS_ABS - 1, max(0, b + ABS_OFF))], 1u);
    atomicMax(&g_minneg, 4096 - b);
}

// ---------------------------------------------------------------- pass 1: histogram + inline table build
__global__ void __launch_bounds__(256) k_hist(const float* __restrict__ xp, int n, double inv_n) {
    __shared__ unsigned char sh8[LBINS * 256];   // 16 KB, per-thread u8 counters
    const int tid  = threadIdx.x;
    const int lane = tid & 31;
    const int wid  = tid >> 5;

    #pragma unroll
    for (int i = 0; i < LBINS / 4; i++)
        ((unsigned int*)sh8)[i * 256 + tid] = 0u;
    __syncthreads();

    const int n4 = n >> 2;
    const float4* x4 = (const float4*)xp;
    const int stride = gridDim.x * blockDim.x;

    for (int i = blockIdx.x * blockDim.x + tid; i < n4; i += 2 * stride) {
        float4 a = x4[i];
        int j = i + stride;
        bool hasb = (j < n4);
        float4 b;
        if (hasb) b = x4[j];

        // magic-number binning: u = bits(RD(5f + 2^23 + 32)); bin l = u - 2^23bits
        unsigned int u0 = __float_as_uint(__fmaf_rd(a.x, 5.0f, MAGIC_F));
        unsigned int u1 = __float_as_uint(__fmaf_rd(a.y, 5.0f, MAGIC_F));
        unsigned int u2 = __float_as_uint(__fmaf_rd(a.z, 5.0f, MAGIC_F));
        unsigned int u3 = __float_as_uint(__fmaf_rd(a.w, 5.0f, MAGIC_F));
        unsigned int l0 = u0 - MAGIC_U, l1 = u1 - MAGIC_U,
                     l2 = u2 - MAGIC_U, l3 = u3 - MAGIC_U;
        if ((l0 | l1 | l2 | l3) < LBINS) {       // all in range (bits only in [0,6))
            sh8[(u0 << 8) + tid]++;              // (u<<8)+tid == l*256+tid (mod 2^32)
            sh8[(u1 << 8) + tid]++;
            sh8[(u2 << 8) + tid]++;
            sh8[(u3 << 8) + tid]++;
        } else {
            if (l0 < LBINS) sh8[(u0 << 8) + tid]++; else hbin_slow(a.x);
            if (l1 < LBINS) sh8[(u1 << 8) + tid]++; else hbin_slow(a.y);
            if (l2 < LBINS) sh8[(u2 << 8) + tid]++; else hbin_slow(a.z);
            if (l3 < LBINS) sh8[(u3 << 8) + tid]++; else hbin_slow(a.w);
        }
        if (hasb) {
            unsigned int v0 = __float_as_uint(__fmaf_rd(b.x, 5.0f, MAGIC_F));
            unsigned int v1 = __float_as_uint(__fmaf_rd(b.y, 5.0f, MAGIC_F));
            unsigned int v2 = __float_as_uint(__fmaf_rd(b.z, 5.0f, MAGIC_F));
            unsigned int v3 = __float_as_uint(__fmaf_rd(b.w, 5.0f, MAGIC_F));
            unsigned int m0 = v0 - MAGIC_U, m1 = v1 - MAGIC_U,
                         m2 = v2 - MAGIC_U, m3 = v3 - MAGIC_U;
            if ((m0 | m1 | m2 | m3) < LBINS) {
                sh8[(v0 << 8) + tid]++;
                sh8[(v1 << 8) + tid]++;
                sh8[(v2 << 8) + tid]++;
                sh8[(v3 << 8) + tid]++;
            } else {
                if (m0 < LBINS) sh8[(v0 << 8) + tid]++; else hbin_slow(b.x);
                if (m1 < LBINS) sh8[(v1 << 8) + tid]++; else hbin_slow(b.y);
                if (m2 < LBINS) sh8[(v2 << 8) + tid]++; else hbin_slow(b.z);
                if (m3 < LBINS) sh8[(v3 << 8) + tid]++; else hbin_slow(b.w);
            }
        }
    }

    // ragged tail (n % 4): block 0 via global atomics
    if (blockIdx.x == 0 && tid < (n & 3)) hbin_slow(xp[(n & ~3) + tid]);
    __syncthreads();

    // merge: warp w handles bin rows w, w+8, ...; dp4a byte-sum
    for (int l = wid; l < LBINS; l += 8) {
        const unsigned int* row = (const unsigned int*)(sh8 + l * 256);
        unsigned int s = __dp4a(row[lane], 0x01010101u, 0u)
                       + __dp4a(row[lane + 32], 0x01010101u, 0u);
        #pragma unroll
        for (int o = 16; o; o >>= 1) s += __shfl_xor_sync(0xFFFFFFFFu, s, o);
        if (lane == 0 && s) atomicAdd(&g_hist[LBASE + l], s);
    }

    // ---- ticket: last block builds the tables ----
    __shared__ unsigned int s_islast;
    if (tid == 0) {
        __threadfence();
        s_islast = (atomicInc(&g_tick1, gridDim.x - 1) == gridDim.x - 1);
    }
    __syncthreads();
    if (!s_islast) return;

    // ============ table build (256 threads) ============
    __shared__ unsigned int s_cum[NBINS_ABS];
    __shared__ unsigned int s_wsum[8];
    __shared__ float s_ha[NHA];
    __shared__ int s_b0;
    if (tid == 0) {
        int mn = g_minneg; g_minneg = 0;
        s_b0 = mn ? (4096 - mn) + ABS_OFF : 0x7FFFFFFF;
    }
    __syncthreads();

    unsigned int h0 = g_hist[4 * tid + 0], h1 = g_hist[4 * tid + 1];
    unsigned int h2 = g_hist[4 * tid + 2], h3 = g_hist[4 * tid + 3];
    g_hist[4 * tid + 0] = 0u; g_hist[4 * tid + 1] = 0u;   // reset for next replay
    g_hist[4 * tid + 2] = 0u; g_hist[4 * tid + 3] = 0u;
    if (h0 | h1 | h2 | h3)
        atomicMin(&s_b0, 4 * tid + (h0 ? 0 : h1 ? 1 : h2 ? 2 : 3));

    unsigned int p0 = h0, p1 = p0 + h1, p2 = p1 + h2, S = p2 + h3;
    unsigned int x = S;
    #pragma unroll
    for (int o = 1; o < 32; o <<= 1) {
        unsigned int y = __shfl_up_sync(0xFFFFFFFFu, x, o);
        if (lane >= o) x += y;
    }
    if (lane == 31) s_wsum[wid] = x;
    unsigned int excl = x - S;
    __syncthreads();
    if (tid == 0) {
        unsigned int a = 0;
        #pragma unroll
        for (int w = 0; w < 8; w++) { unsigned int t = s_wsum[w]; s_wsum[w] = a; a += t; }
    }
    __syncthreads();
    unsigned int base_off = s_wsum[wid] + excl;
    s_cum[4 * tid + 0] = base_off + p0;
    s_cum[4 * tid + 1] = base_off + p1;
    s_cum[4 * tid + 2] = base_off + p2;
    s_cum[4 * tid + 3] = base_off + S;
    __syncthreads();

    const unsigned int total = s_cum[NBINS_ABS - 1];
    int b0rel = s_b0 - ABS_OFF;                 // floor(5 * xmin)
    int fd = (b0rel >= 0) ? (b0rel / 5) : -((-b0rel + 4) / 5);
    int vmin_i = fd - 1;
    int hbase = 5 * vmin_i + ABS_OFF;

    if (tid < NHA) {
        int j = tid;
        double lo, hi;
        if (j == 0) lo = 0.0;
        else {
            int k = hbase + j - 1;
            lo = (k < 0) ? 0.0 : (double)((k >= NBINS_ABS) ? total : s_cum[k]);
        }
        if (j >= NHA - 1) hi = (double)total;
        else {
            int k = hbase + j + 4;
            hi = (k < 0) ? 0.0 : (double)((k >= NBINS_ABS) ? total : s_cum[k]);
        }
        s_ha[j] = (float)((hi - lo) * inv_n);
    }
    __syncthreads();
    if (tid < NTAB) {
        float A = s_ha[tid + 1] - s_ha[tid];
        float B = (float)((double)s_ha[tid] + 1e-8 - (double)tid * (double)A);
        g_table[tid] = make_float2(A, B);
    }
    if (tid == 0) g_nvmn5 = -(((float)vmin_i + 0.5f) * 5.0f);
}

// ---------------------------------------------------------------- pass 2: loss + inline finalize
static __device__ __forceinline__ float nloss_of(float xv, float nvmn5, const float2* tab) {
    float t = fmaf(xv, 5.0f, nvmn5);     // >= 2.5 since x >= min
    int i = min(__float2int_rd(t), NTAB - 1);
    float2 ab = tab[i];
    return fmaf(t, ab.x, ab.y);
}

static __device__ __forceinline__ void prod4(const float4& v, float nvmn5,
                                             const float2* tab, int& e, float& m) {
    float p = nloss_of(v.x, nvmn5, tab) * nloss_of(v.y, nvmn5, tab)
            * nloss_of(v.z, nvmn5, tab) * nloss_of(v.w, nvmn5, tab);
    unsigned int ub = __float_as_uint(p);
    e = (int)(ub >> 23) - 127;
    m = __uint_as_float((ub & 0x007FFFFFu) | 0x3F800000u);
}

__global__ void __launch_bounds__(256) k_loss(const float* __restrict__ xp, int n,
                                              double inv_n, float* __restrict__ out) {
    __shared__ float2 tab[NTAB];
    for (int i = threadIdx.x; i < NTAB; i += blockDim.x) tab[i] = g_table[i];
    __syncthreads();
    const float nvmn5 = g_nvmn5;

    const int n4 = n >> 2;
    const float4* x4 = (const float4*)xp;
    const int tid = blockIdx.x * blockDim.x + threadIdx.x;
    const int stride = gridDim.x * blockDim.x;

    float acc = 0.0f;
    // REVERSE traversal: hit what k_hist left resident in L2.
    for (int i = tid; i < n4; i += 2 * stride) {
        float4 a = x4[n4 - 1 - i];
        int ea; float ma;
        prod4(a, nvmn5, tab, ea, ma);
        int j = i + stride;
        if (j < n4) {
            float4 b = x4[n4 - 1 - j];
            int eb; float mb;
            prod4(b, nvmn5, tab, eb, mb);
            acc += (float)(ea + eb) + __log2f(ma * mb);
        } else {
            acc += (float)ea + __log2f(ma);
        }
    }
    if (blockIdx.x == 0 && threadIdx.x < (n & 3)) {
        float f = xp[(n & ~3) + threadIdx.x];
        acc += __log2f(nloss_of(f, nvmn5, tab));
    }

    #pragma unroll
    for (int o = 16; o; o >>= 1) acc += __shfl_xor_sync(0xFFFFFFFFu, acc, o);
    __shared__ float ws[8];
    if ((threadIdx.x & 31) == 0) ws[threadIdx.x >> 5] = acc;
    __syncthreads();
    if (threadIdx.x < 32) {
        float a = (threadIdx.x < (blockDim.x >> 5)) ? ws[threadIdx.x] : 0.0f;
        #pragma unroll
        for (int o = 4; o; o >>= 1) a += __shfl_xor_sync(0xFFFFFFFFu, a, o);
        if (threadIdx.x == 0) atomicAdd(&g_acc, (double)a);
    }

    // ---- ticket: last block finalizes ----
    __shared__ unsigned int s_islast;
    if (threadIdx.x == 0) {
        __threadfence();
        s_islast = (atomicInc(&g_tick2, gridDim.x - 1) == gridDim.x - 1);
    }
    __syncthreads();
    if (s_islast && threadIdx.x == 0) {
        double a = g_acc;
        g_acc = 0.0;
        out[0] = (float)(-a * inv_n);
    }
}

// ---------------------------------------------------------------- launch
extern "C" void kernel_launch(void* const* d_in, const int* in_sizes, int n_in,
                              void* d_out, int out_size) {
    const float* x = (const float*)d_in[0];
    const int n = in_sizes[0];
    const double inv_n = 1.0 / (double)n;

    k_hist<<<GRID_N, 256>>>(x, n, inv_n);
    k_loss<<<GRID_N, 256>>>(x, n, inv_n, (float*)d_out);
}

// round 6
// speedup vs baseline: 2.0021x; 1.0051x over previous
#include <cuda_runtime.h>
#include <math_constants.h>

#define NBINS_ABS 1024
#define ABS_OFF   512
#define NTAB      195
#define NHA       196
#define LBINS     64                 // local bins: floor(5x) in [-32,31]
#define MAGIC_F   8388640.0f         // 2^23 + 32
#define MAGIC_U   0x4B000000u        // bits(2^23)
#define GRID_N    1184

__device__ unsigned int g_hist[NBINS_ABS];
__device__ int          g_minneg;    // max over outliers of (4096 - floor(5x)); 0 = none
__device__ double       g_acc;
__device__ float2       g_table[NTAB];   // (A, B): nloss = t*A + B
__device__ float        g_nvmn5;         // -(vmin+0.5)*5
__device__ unsigned int g_tick1;
__device__ unsigned int g_tick2;

// ---------------------------------------------------------------- slow path
static __device__ __noinline__ void hbin_slow(float f) {
    int b = __float2int_rd(f * 5.0f);
    atomicAdd(&g_hist[min(NBINS_ABS - 1, max(0, b + ABS_OFF))], 1u);
    atomicMax(&g_minneg, 4096 - b);
}

// swizzled per-thread u8 counter address: l*256 + (tid ^ ((l&63)<<2))
// bank = ((tid>>2) ^ l) & 31 -> depends on bin, kills systematic conflicts.
// (u<<8) == l*256 mod 2^32 and (u<<2)&0xFC == (l&63)<<2 (magic-number trick).
static __device__ __forceinline__ unsigned int haddr(unsigned int u, int tid) {
    return (u << 8) + (unsigned int)(tid ^ (int)((u << 2) & 0xFCu));
}

// ---------------------------------------------------------------- pass 1: histogram + inline table build
__global__ void __launch_bounds__(256) k_hist(const float* __restrict__ xp, int n, double inv_n) {
    __shared__ unsigned char sh8[LBINS * 256];   // 16 KB, per-thread u8 counters (swizzled)
    const int tid  = threadIdx.x;
    const int lane = tid & 31;
    const int wid  = tid >> 5;

    #pragma unroll
    for (int i = 0; i < LBINS / 4; i++)
        ((unsigned int*)sh8)[i * 256 + tid] = 0u;
    __syncthreads();

    const int n4 = n >> 2;
    const float4* x4 = (const float4*)xp;
    const int stride = gridDim.x * blockDim.x;

    for (int i = blockIdx.x * blockDim.x + tid; i < n4; i += 2 * stride) {
        float4 a = x4[i];
        int j = i + stride;
        bool hasb = (j < n4);
        float4 b;
        if (hasb) b = x4[j];

        unsigned int u0 = __float_as_uint(__fmaf_rd(a.x, 5.0f, MAGIC_F));
        unsigned int u1 = __float_as_uint(__fmaf_rd(a.y, 5.0f, MAGIC_F));
        unsigned int u2 = __float_as_uint(__fmaf_rd(a.z, 5.0f, MAGIC_F));
        unsigned int u3 = __float_as_uint(__fmaf_rd(a.w, 5.0f, MAGIC_F));
        unsigned int l0 = u0 - MAGIC_U, l1 = u1 - MAGIC_U,
                     l2 = u2 - MAGIC_U, l3 = u3 - MAGIC_U;
        if ((l0 | l1 | l2 | l3) < LBINS) {
            sh8[haddr(u0, tid)]++;
            sh8[haddr(u1, tid)]++;
            sh8[haddr(u2, tid)]++;
            sh8[haddr(u3, tid)]++;
        } else {
            if (l0 < LBINS) sh8[haddr(u0, tid)]++; else hbin_slow(a.x);
            if (l1 < LBINS) sh8[haddr(u1, tid)]++; else hbin_slow(a.y);
            if (l2 < LBINS) sh8[haddr(u2, tid)]++; else hbin_slow(a.z);
            if (l3 < LBINS) sh8[haddr(u3, tid)]++; else hbin_slow(a.w);
        }
        if (hasb) {
            unsigned int v0 = __float_as_uint(__fmaf_rd(b.x, 5.0f, MAGIC_F));
            unsigned int v1 = __float_as_uint(__fmaf_rd(b.y, 5.0f, MAGIC_F));
            unsigned int v2 = __float_as_uint(__fmaf_rd(b.z, 5.0f, MAGIC_F));
            unsigned int v3 = __float_as_uint(__fmaf_rd(b.w, 5.0f, MAGIC_F));
            unsigned int m0 = v0 - MAGIC_U, m1 = v1 - MAGIC_U,
                         m2 = v2 - MAGIC_U, m3 = v3 - MAGIC_U;
            if ((m0 | m1 | m2 | m3) < LBINS) {
                sh8[haddr(v0, tid)]++;
                sh8[haddr(v1, tid)]++;
                sh8[haddr(v2, tid)]++;
                sh8[haddr(v3, tid)]++;
            } else {
                if (m0 < LBINS) sh8[haddr(v0, tid)]++; else hbin_slow(b.x);
                if (m1 < LBINS) sh8[haddr(v1, tid)]++; else hbin_slow(b.y);
                if (m2 < LBINS) sh8[haddr(v2, tid)]++; else hbin_slow(b.z);
                if (m3 < LBINS) sh8[haddr(v3, tid)]++; else hbin_slow(b.w);
            }
        }
    }
    if (blockIdx.x == 0 && tid < (n & 3)) hbin_slow(xp[(n & ~3) + tid]);
    __syncthreads();

    // merge (swizzle permutes bytes within a row; row-sum is order-blind)
    for (int l = wid; l < LBINS; l += 8) {
        const unsigned int* row = (const unsigned int*)(sh8 + l * 256);
        unsigned int s = __dp4a(row[lane], 0x01010101u, 0u)
                       + __dp4a(row[lane + 32], 0x01010101u, 0u);
        #pragma unroll
        for (int o = 16; o; o >>= 1) s += __shfl_xor_sync(0xFFFFFFFFu, s, o);
        if (lane == 0 && s) atomicAdd(&g_hist[(ABS_OFF - 32) + l], s);
    }

    // ---- ticket: last block builds the tables ----
    __shared__ unsigned int s_islast;
    if (tid == 0) {
        __threadfence();
        s_islast = (atomicInc(&g_tick1, gridDim.x - 1) == gridDim.x - 1);
    }
    __syncthreads();
    if (!s_islast) return;

    // ============ table build (256 threads, last block only) ============
    __shared__ unsigned int s_cum[NBINS_ABS];
    __shared__ unsigned int s_wsum[8];
    __shared__ float s_ha[NHA];
    __shared__ int s_b0;
    if (tid == 0) {
        int mn = g_minneg; g_minneg = 0;
        s_b0 = mn ? (4096 - mn) + ABS_OFF : 0x7FFFFFFF;
    }
    __syncthreads();

    unsigned int h0 = g_hist[4 * tid + 0], h1 = g_hist[4 * tid + 1];
    unsigned int h2 = g_hist[4 * tid + 2], h3 = g_hist[4 * tid + 3];
    g_hist[4 * tid + 0] = 0u; g_hist[4 * tid + 1] = 0u;   // reset for next replay
    g_hist[4 * tid + 2] = 0u; g_hist[4 * tid + 3] = 0u;
    if (h0 | h1 | h2 | h3)
        atomicMin(&s_b0, 4 * tid + (h0 ? 0 : h1 ? 1 : h2 ? 2 : 3));

    unsigned int p0 = h0, p1 = p0 + h1, p2 = p1 + h2, S = p2 + h3;
    unsigned int x = S;
    #pragma unroll
    for (int o = 1; o < 32; o <<= 1) {
        unsigned int y = __shfl_up_sync(0xFFFFFFFFu, x, o);
        if (lane >= o) x += y;
    }
    if (lane == 31) s_wsum[wid] = x;
    unsigned int excl = x - S;
    __syncthreads();
    if (tid == 0) {
        unsigned int a = 0;
        #pragma unroll
        for (int w = 0; w < 8; w++) { unsigned int t = s_wsum[w]; s_wsum[w] = a; a += t; }
    }
    __syncthreads();
    unsigned int boff = s_wsum[wid] + excl;
    s_cum[4 * tid + 0] = boff + p0;
    s_cum[4 * tid + 1] = boff + p1;
    s_cum[4 * tid + 2] = boff + p2;
    s_cum[4 * tid + 3] = boff + S;
    __syncthreads();

    const unsigned int total = s_cum[NBINS_ABS - 1];
    int b0rel = s_b0 - ABS_OFF;                 // floor(5 * xmin)
    int fd = (b0rel >= 0) ? (b0rel / 5) : -((-b0rel + 4) / 5);
    int vmin_i = fd - 1;
    int hbase = 5 * vmin_i + ABS_OFF;

    if (tid < NHA) {
        int j = tid;
        double lo, hi;
        if (j == 0) lo = 0.0;
        else {
            int k = hbase + j - 1;
            lo = (k < 0) ? 0.0 : (double)((k >= NBINS_ABS) ? total : s_cum[k]);
        }
        if (j >= NHA - 1) hi = (double)total;
        else {
            int k = hbase + j + 4;
            hi = (k < 0) ? 0.0 : (double)((k >= NBINS_ABS) ? total : s_cum[k]);
        }
        s_ha[j] = (float)((hi - lo) * inv_n);
    }
    __syncthreads();
    if (tid < NTAB) {
        float A = s_ha[tid + 1] - s_ha[tid];
        float B = (float)((double)s_ha[tid] + 1e-8 - (double)tid * (double)A);
        g_table[tid] = make_float2(A, B);
    }
    if (tid == 0) g_nvmn5 = -(((float)vmin_i + 0.5f) * 5.0f);
}

// ---------------------------------------------------------------- pass 2: loss + inline finalize
static __device__ __forceinline__ float nloss_of(float xv, float nvmn5, const float2* tab) {
    float t = fmaf(xv, 5.0f, nvmn5);     // >= 2.5 since x >= min
    int i = min(__float2int_rd(t), NTAB - 1);
    float2 ab = tab[i];
    return fmaf(t, ab.x, ab.y);
}

static __device__ __forceinline__ void prod4(const float4& v, float nvmn5,
                                             const float2* tab, int& e, float& m) {
    float p = nloss_of(v.x, nvmn5, tab) * nloss_of(v.y, nvmn5, tab)
            * nloss_of(v.z, nvmn5, tab) * nloss_of(v.w, nvmn5, tab);
    unsigned int ub = __float_as_uint(p);
    e = (int)(ub >> 23) - 127;
    m = __uint_as_float((ub & 0x007FFFFFu) | 0x3F800000u);
}

__global__ void __launch_bounds__(256) k_loss(const float* __restrict__ xp, int n,
                                              double inv_n, float* __restrict__ out) {
    __shared__ float2 tab[NTAB];
    for (int i = threadIdx.x; i < NTAB; i += blockDim.x) tab[i] = g_table[i];
    __syncthreads();
    const float nvmn5 = g_nvmn5;

    const int n4 = n >> 2;
    const float4* x4 = (const float4*)xp;
    const int tid = blockIdx.x * blockDim.x + threadIdx.x;
    const int stride = gridDim.x * blockDim.x;

    float acc = 0.0f;
    // reverse traversal: hit what k_hist left resident in L2
    for (int i = tid; i < n4; i += 2 * stride) {
        float4 a = x4[n4 - 1 - i];
        int ea; float ma;
        prod4(a, nvmn5, tab, ea, ma);
        int j = i + stride;
        if (j < n4) {
            float4 b = x4[n4 - 1 - j];
            int eb; float mb;
            prod4(b, nvmn5, tab, eb, mb);
            acc += (float)(ea + eb) + __log2f(ma * mb);
        } else {
            acc += (float)ea + __log2f(ma);
        }
    }
    if (blockIdx.x == 0 && threadIdx.x < (n & 3)) {
        float f = xp[(n & ~3) + threadIdx.x];
        acc += __log2f(nloss_of(f, nvmn5, tab));
    }

    #pragma unroll
    for (int o = 16; o; o >>= 1) acc += __shfl_xor_sync(0xFFFFFFFFu, acc, o);
    __shared__ float ws[8];
    if ((threadIdx.x & 31) == 0) ws[threadIdx.x >> 5] = acc;
    __syncthreads();
    if (threadIdx.x < 32) {
        float a = (threadIdx.x < (blockDim.x >> 5)) ? ws[threadIdx.x] : 0.0f;
        #pragma unroll
        for (int o = 4; o; o >>= 1) a += __shfl_xor_sync(0xFFFFFFFFu, a, o);
        if (threadIdx.x == 0) atomicAdd(&g_acc, (double)a);
    }

    // ---- ticket: last block finalizes ----
    if (threadIdx.x == 0) {
        __threadfence();
        if (atomicInc(&g_tick2, gridDim.x - 1) == gridDim.x - 1) {
            double a = g_acc;
            g_acc = 0.0;
            out[0] = (float)(-a * inv_n);
        }
    }
}

// ---------------------------------------------------------------- launch
extern "C" void kernel_launch(void* const* d_in, const int* in_sizes, int n_in,
                              void* d_out, int out_size) {
    const float* x = (const float*)d_in[0];
    const int n = in_sizes[0];
    const double inv_n = 1.0 / (double)n;

    k_hist<<<GRID_N, 256>>>(x, n, inv_n);
    k_loss<<<GRID_N, 256>>>(x, n, inv_n, (float*)d_out);
}

// round 7
// speedup vs baseline: 2.1656x; 1.0817x over previous
#include <cuda_runtime.h>

#define NBINS_ABS 1024
#define ABS_OFF   512
#define NTAB      195
#define NHA       196
#define LBINS     64                 // local bins: floor(5x) in [-32,31]
#define MAGIC_F   8388640.0f         // 2^23 + 32
#define MAGIC_U   0x4B000000u        // bits(2^23)
#define GRID_H    740                // 148 SMs * 5
#define GRID_L    740

__device__ unsigned int g_hist[NBINS_ABS];
__device__ int          g_minneg;    // max over outliers of (4096 - floor(5x)); 0 = none
__device__ double       g_acc;
__device__ unsigned int g_tick;

// ---------------------------------------------------------------- slow path
static __device__ __noinline__ void hbin_slow(float f) {
    int b = __float2int_rd(f * 5.0f);
    atomicAdd(&g_hist[min(NBINS_ABS - 1, max(0, b + ABS_OFF))], 1u);
    atomicMax(&g_minneg, 4096 - b);
}

// ---------------------------------------------------------------- pass 1: histogram only
static __device__ __forceinline__ void hquad(const float4& a, unsigned char* sh8, int tid,
                                             float fx, float fy, float fz, float fw) {
    (void)fx; (void)fy; (void)fz; (void)fw;
}

static __device__ __forceinline__ void hq(const float4& a, unsigned char* sh8, int tid) {
    unsigned int u0 = __float_as_uint(__fmaf_rd(a.x, 5.0f, MAGIC_F));
    unsigned int u1 = __float_as_uint(__fmaf_rd(a.y, 5.0f, MAGIC_F));
    unsigned int u2 = __float_as_uint(__fmaf_rd(a.z, 5.0f, MAGIC_F));
    unsigned int u3 = __float_as_uint(__fmaf_rd(a.w, 5.0f, MAGIC_F));
    unsigned int l0 = u0 - MAGIC_U, l1 = u1 - MAGIC_U,
                 l2 = u2 - MAGIC_U, l3 = u3 - MAGIC_U;
    if ((l0 | l1 | l2 | l3) < LBINS) {      // all in range (bits only in [0,6))
        sh8[(u0 << 8) + tid]++;             // (u<<8)+tid == l*256+tid (mod 2^32)
        sh8[(u1 << 8) + tid]++;
        sh8[(u2 << 8) + tid]++;
        sh8[(u3 << 8) + tid]++;
    } else {
        if (l0 < LBINS) sh8[(u0 << 8) + tid]++; else hbin_slow(a.x);
        if (l1 < LBINS) sh8[(u1 << 8) + tid]++; else hbin_slow(a.y);
        if (l2 < LBINS) sh8[(u2 << 8) + tid]++; else hbin_slow(a.z);
        if (l3 < LBINS) sh8[(u3 << 8) + tid]++; else hbin_slow(a.w);
    }
}

__global__ void __launch_bounds__(256, 5) k_hist(const float* __restrict__ xp, int n) {
    __shared__ unsigned char sh8[LBINS * 256];   // 16 KB per-thread u8 counters
    const int tid  = threadIdx.x;
    const int lane = tid & 31;
    const int wid  = tid >> 5;

    #pragma unroll
    for (int i = 0; i < LBINS / 4; i++)
        ((unsigned int*)sh8)[i * 256 + tid] = 0u;
    __syncthreads();

    const int n4 = n >> 2;
    const float4* x4 = (const float4*)xp;
    const int stride = gridDim.x * blockDim.x;
    const int per = 4 * stride;
    const int nfull = n4 / per;

    int i = blockIdx.x * blockDim.x + tid;
    for (int it = 0; it < nfull; ++it, i += per) {
        float4 a = x4[i];
        float4 b = x4[i + stride];
        float4 c = x4[i + 2 * stride];
        float4 d = x4[i + 3 * stride];
        hq(a, sh8, tid);
        hq(b, sh8, tid);
        hq(c, sh8, tid);
        hq(d, sh8, tid);
    }
    for (; i < n4; i += stride) {           // ragged sub-streams
        float4 a = x4[i];
        hq(a, sh8, tid);
    }
    if (blockIdx.x == 0 && tid < (n & 3)) hbin_slow(xp[(n & ~3) + tid]);
    __syncthreads();

    // merge: warp w handles bin rows w, w+8, ...; dp4a byte-sum (order-blind)
    for (int l = wid; l < LBINS; l += 8) {
        const unsigned int* row = (const unsigned int*)(sh8 + l * 256);
        unsigned int s = __dp4a(row[lane], 0x01010101u, 0u)
                       + __dp4a(row[lane + 32], 0x01010101u, 0u);
        #pragma unroll
        for (int o = 16; o; o >>= 1) s += __shfl_xor_sync(0xFFFFFFFFu, s, o);
        if (lane == 0 && s) atomicAdd(&g_hist[(ABS_OFF - 32) + l], s);
    }
}

// ---------------------------------------------------------------- pass 2: per-block table build + loss
static __device__ __forceinline__ float nloss_of(float xv, float nvmn5, const float2* tab) {
    float t = fmaf(xv, 5.0f, nvmn5);     // >= 2.5 since x >= min
    int i = min(__float2int_rd(t), NTAB - 1);
    float2 ab = tab[i];
    return fmaf(t, ab.x, ab.y);
}

static __device__ __forceinline__ float pairloss(const float4& a, const float4& b,
                                                 float nvmn5, const float2* tab) {
    float pa = nloss_of(a.x, nvmn5, tab) * nloss_of(a.y, nvmn5, tab)
             * nloss_of(a.z, nvmn5, tab) * nloss_of(a.w, nvmn5, tab);
    float pb = nloss_of(b.x, nvmn5, tab) * nloss_of(b.y, nvmn5, tab)
             * nloss_of(b.z, nvmn5, tab) * nloss_of(b.w, nvmn5, tab);
    unsigned int ua = __float_as_uint(pa);
    unsigned int ub = __float_as_uint(pb);
    int e = ((int)(ua >> 23) - 127) + ((int)(ub >> 23) - 127);
    float m = __uint_as_float((ua & 0x007FFFFFu) | 0x3F800000u)
            * __uint_as_float((ub & 0x007FFFFFu) | 0x3F800000u);   // in [1,4)
    return (float)e + __log2f(m);
}

__global__ void __launch_bounds__(256, 5) k_loss(const float* __restrict__ xp, int n,
                                                 double inv_n, float* __restrict__ out) {
    __shared__ unsigned int s_cum[NBINS_ABS];
    __shared__ unsigned int s_wsum[8];
    __shared__ float  s_ha[NHA];
    __shared__ float2 s_tab[NTAB];
    __shared__ float  s_nvmn5;
    __shared__ int    s_b0;
    __shared__ unsigned int s_islast;
    __shared__ float  ws[8];
    const int tid  = threadIdx.x;
    const int lane = tid & 31;
    const int wid  = tid >> 5;

    // ---- prologue: every block rebuilds the table from g_hist ----
    if (tid == 0) {
        int mn = g_minneg;
        s_b0 = mn ? (4096 - mn) + ABS_OFF : 0x7FFFFFFF;
    }
    __syncthreads();

    unsigned int h0 = g_hist[4 * tid + 0], h1 = g_hist[4 * tid + 1];
    unsigned int h2 = g_hist[4 * tid + 2], h3 = g_hist[4 * tid + 3];
    if (h0 | h1 | h2 | h3)
        atomicMin(&s_b0, 4 * tid + (h0 ? 0 : h1 ? 1 : h2 ? 2 : 3));

    unsigned int p0 = h0, p1 = p0 + h1, p2 = p1 + h2, S = p2 + h3;
    unsigned int x = S;
    #pragma unroll
    for (int o = 1; o < 32; o <<= 1) {
        unsigned int y = __shfl_up_sync(0xFFFFFFFFu, x, o);
        if (lane >= o) x += y;
    }
    if (lane == 31) s_wsum[wid] = x;
    unsigned int excl = x - S;
    __syncthreads();
    if (tid == 0) {
        unsigned int a = 0;
        #pragma unroll
        for (int w = 0; w < 8; w++) { unsigned int t = s_wsum[w]; s_wsum[w] = a; a += t; }
    }
    __syncthreads();
    unsigned int boff = s_wsum[wid] + excl;
    s_cum[4 * tid + 0] = boff + p0;
    s_cum[4 * tid + 1] = boff + p1;
    s_cum[4 * tid + 2] = boff + p2;
    s_cum[4 * tid + 3] = boff + S;
    __syncthreads();

    const unsigned int total = s_cum[NBINS_ABS - 1];
    int b0rel = s_b0 - ABS_OFF;                 // floor(5 * xmin)
    int fd = (b0rel >= 0) ? (b0rel / 5) : -((-b0rel + 4) / 5);
    int vmin_i = fd - 1;
    int hbase = 5 * vmin_i + ABS_OFF;

    if (tid < NHA) {
        int j = tid;
        double lo, hi;
        if (j == 0) lo = 0.0;
        else {
            int k = hbase + j - 1;
            lo = (k < 0) ? 0.0 : (double)((k >= NBINS_ABS) ? total : s_cum[k]);
        }
        if (j >= NHA - 1) hi = (double)total;
        else {
            int k = hbase + j + 4;
            hi = (k < 0) ? 0.0 : (double)((k >= NBINS_ABS) ? total : s_cum[k]);
        }
        s_ha[j] = (float)((hi - lo) * inv_n);
    }
    __syncthreads();
    if (tid < NTAB) {
        float A = s_ha[tid + 1] - s_ha[tid];
        float B = (float)((double)s_ha[tid] + 1e-8 - (double)tid * (double)A);
        s_tab[tid] = make_float2(A, B);
    }
    if (tid == 0) s_nvmn5 = -(((float)vmin_i + 0.5f) * 5.0f);
    __syncthreads();

    const float nvmn5 = s_nvmn5;
    const float2* tab = s_tab;

    // ---- main loss loop: reverse traversal, software prefetch ----
    const int n4 = n >> 2;
    const float4* p = (const float4*)xp + (n4 - 1);
    const int stride = gridDim.x * blockDim.x;
    const int per = 2 * stride;
    const int nfull = n4 / per;

    float acc = 0.0f;
    int i = blockIdx.x * blockDim.x + tid;
    float4 a = p[-i];
    float4 b = p[-(i + stride)];
    for (int it = 1; it < nfull; ++it) {
        int i2 = i + per;
        float4 a2 = p[-i2];
        float4 b2 = p[-(i2 + stride)];
        acc += pairloss(a, b, nvmn5, tab);
        a = a2; b = b2; i = i2;
    }
    acc += pairloss(a, b, nvmn5, tab);
    i += per;
    for (; i < n4; i += stride) {               // ragged sub-streams
        float4 c = p[-i];
        float pc = nloss_of(c.x, nvmn5, tab) * nloss_of(c.y, nvmn5, tab)
                 * nloss_of(c.z, nvmn5, tab) * nloss_of(c.w, nvmn5, tab);
        unsigned int uc = __float_as_uint(pc);
        acc += (float)((int)(uc >> 23) - 127)
             + __log2f(__uint_as_float((uc & 0x007FFFFFu) | 0x3F800000u));
    }
    if (blockIdx.x == 0 && tid < (n & 3)) {
        float f = xp[(n & ~3) + tid];
        acc += __log2f(nloss_of(f, nvmn5, tab));
    }

    // ---- reduce ----
    #pragma unroll
    for (int o = 16; o; o >>= 1) acc += __shfl_xor_sync(0xFFFFFFFFu, acc, o);
    if (lane == 0) ws[wid] = acc;
    __syncthreads();
    if (tid < 32) {
        float a2 = (tid < 8) ? ws[tid] : 0.0f;
        #pragma unroll
        for (int o = 4; o; o >>= 1) a2 += __shfl_xor_sync(0xFFFFFFFFu, a2, o);
        if (tid == 0) atomicAdd(&g_acc, (double)a2);
    }

    // ---- ticket: last block finalizes + resets all replay state ----
    if (tid == 0) {
        __threadfence();
        s_islast = (atomicInc(&g_tick, gridDim.x - 1) == gridDim.x - 1);
    }
    __syncthreads();
    if (s_islast) {
        for (int k = tid; k < NBINS_ABS; k += 256) g_hist[k] = 0u;
        if (tid == 0) {
            g_minneg = 0;
            double a3 = g_acc;
            g_acc = 0.0;
            out[0] = (float)(-a3 * inv_n);
        }
    }
}

// ---------------------------------------------------------------- launch
extern "C" void kernel_launch(void* const* d_in, const int* in_sizes, int n_in,
                              void* d_out, int out_size) {
    const float* x = (const float*)d_in[0];
    const int n = in_sizes[0];
    const double inv_n = 1.0 / (double)n;

    k_hist<<<GRID_H, 256>>>(x, n);
    k_loss<<<GRID_L, 256>>>(x, n, inv_n, (float*)d_out);
}

// round 8
// speedup vs baseline: 2.3735x; 1.0960x over previous
#include <cuda_runtime.h>

#define NBINS_ABS 1024
#define ABS_OFF   512
#define NTAB      195
#define NHA       196
#define LBINS     64                 // local bins: floor(5x) in [-32,31]
#define LBASE     (ABS_OFF - 32)
#define MAGIC_F   8388640.0f         // 2^23 + 32
#define MAGIC_U   0x4B000000u        // bits(2^23)
#define GRID_N    1184               // 148 SMs * 8

__device__ unsigned int g_hist[NBINS_ABS];
__device__ int          g_minneg;    // max over outliers of (4096 - floor(5x)); 0 = none
__device__ double       g_acc;
__device__ unsigned int g_tick;

// ---------------------------------------------------------------- slow path
static __device__ __noinline__ void hbin_slow(float f) {
    int b = __float2int_rd(f * 5.0f);
    atomicAdd(&g_hist[min(NBINS_ABS - 1, max(0, b + ABS_OFF))], 1u);
    atomicMax(&g_minneg, 4096 - b);
}

// conflict-free per-thread byte counter: each thread owns word (l>>2)*256+tid,
// byte (l&3).  byte addr = ((l>>2)<<10) + (tid<<2) + (l&3)
//            = ((u&0xFC)<<8) + (u&3) + (tid<<2)     [magic: low byte of MAGIC_U is 0]
// bank = tid&31  -> every lane its own bank, ALWAYS, regardless of bin.
static __device__ __forceinline__ unsigned int haddr(unsigned int u, int tq) {
    return ((u & 0xFCu) << 8) + (u & 3u) + (unsigned int)tq;
}

static __device__ __forceinline__ void hq(const float4& a, unsigned char* sh8, int tq) {
    unsigned int u0 = __float_as_uint(__fmaf_rd(a.x, 5.0f, MAGIC_F));
    unsigned int u1 = __float_as_uint(__fmaf_rd(a.y, 5.0f, MAGIC_F));
    unsigned int u2 = __float_as_uint(__fmaf_rd(a.z, 5.0f, MAGIC_F));
    unsigned int u3 = __float_as_uint(__fmaf_rd(a.w, 5.0f, MAGIC_F));
    unsigned int l0 = u0 - MAGIC_U, l1 = u1 - MAGIC_U,
                 l2 = u2 - MAGIC_U, l3 = u3 - MAGIC_U;
    if ((l0 | l1 | l2 | l3) < LBINS) {      // all in range (bits only in [0,6))
        sh8[haddr(u0, tq)]++;
        sh8[haddr(u1, tq)]++;
        sh8[haddr(u2, tq)]++;
        sh8[haddr(u3, tq)]++;
    } else {
        if (l0 < LBINS) sh8[haddr(u0, tq)]++; else hbin_slow(a.x);
        if (l1 < LBINS) sh8[haddr(u1, tq)]++; else hbin_slow(a.y);
        if (l2 < LBINS) sh8[haddr(u2, tq)]++; else hbin_slow(a.z);
        if (l3 < LBINS) sh8[haddr(u3, tq)]++; else hbin_slow(a.w);
    }
}

// ---------------------------------------------------------------- pass 1: histogram
__global__ void __launch_bounds__(256, 8) k_hist(const float* __restrict__ xp, int n) {
    __shared__ unsigned char sh8[16 * 1024];     // 16 rows x 256 words x 4 bins
    const int tid  = threadIdx.x;
    const int lane = tid & 31;
    const int wid  = tid >> 5;
    const int tq   = tid << 2;

    #pragma unroll
    for (int i = 0; i < 16; i++)
        ((unsigned int*)sh8)[i * 256 + tid] = 0u;
    __syncthreads();

    const int n4 = n >> 2;
    const float4* x4 = (const float4*)xp;
    const int stride = gridDim.x * blockDim.x;
    const int per = 2 * stride;
    const int nfull = n4 / per;

    int i = blockIdx.x * blockDim.x + tid;
    for (int it = 0; it < nfull; ++it, i += per) {
        float4 a = x4[i];
        float4 b = x4[i + stride];
        hq(a, sh8, tq);
        hq(b, sh8, tq);
    }
    for (; i < n4; i += stride) {
        float4 a = x4[i];
        hq(a, sh8, tq);
    }
    if (blockIdx.x == 0 && tid < (n & 3)) hbin_slow(xp[(n & ~3) + tid]);
    __syncthreads();

    // merge: row r holds bins 4r..4r+3; per-byte extraction via dp4a
    for (int r = wid; r < 16; r += 8) {
        const unsigned int* row = (const unsigned int*)sh8 + r * 256;
        unsigned int a0 = 0, a1 = 0, a2 = 0, a3 = 0;
        #pragma unroll
        for (int j = 0; j < 8; j++) {
            unsigned int w = row[lane + 32 * j];
            a0 = __dp4a(w, 0x00000001u, a0);
            a1 = __dp4a(w, 0x00000100u, a1);
            a2 = __dp4a(w, 0x00010000u, a2);
            a3 = __dp4a(w, 0x01000000u, a3);
        }
        #pragma unroll
        for (int o = 16; o; o >>= 1) {
            a0 += __shfl_xor_sync(0xFFFFFFFFu, a0, o);
            a1 += __shfl_xor_sync(0xFFFFFFFFu, a1, o);
            a2 += __shfl_xor_sync(0xFFFFFFFFu, a2, o);
            a3 += __shfl_xor_sync(0xFFFFFFFFu, a3, o);
        }
        if (lane == 0) {
            int b = LBASE + 4 * r;
            if (a0) atomicAdd(&g_hist[b + 0], a0);
            if (a1) atomicAdd(&g_hist[b + 1], a1);
            if (a2) atomicAdd(&g_hist[b + 2], a2);
            if (a3) atomicAdd(&g_hist[b + 3], a3);
        }
    }
}

// ---------------------------------------------------------------- pass 2: per-block table build + loss
static __device__ __forceinline__ float nloss_of(float xv, float nvmn5, const float2* tab) {
    float t = fmaf(xv, 5.0f, nvmn5);     // >= 2.5 since x >= min
    int i = min(__float2int_rd(t), NTAB - 1);
    float2 ab = tab[i];
    return fmaf(t, ab.x, ab.y);
}

static __device__ __forceinline__ void prod4(const float4& v, float nvmn5,
                                             const float2* tab, int& e, float& m) {
    float p = nloss_of(v.x, nvmn5, tab) * nloss_of(v.y, nvmn5, tab)
            * nloss_of(v.z, nvmn5, tab) * nloss_of(v.w, nvmn5, tab);
    unsigned int ub = __float_as_uint(p);
    e = (int)(ub >> 23) - 127;
    m = __uint_as_float((ub & 0x007FFFFFu) | 0x3F800000u);
}

__global__ void __launch_bounds__(256, 8) k_loss(const float* __restrict__ xp, int n,
                                                 double inv_n, float* __restrict__ out) {
    __shared__ unsigned int s_cum[NBINS_ABS];
    __shared__ unsigned int s_wsum[8];
    __shared__ float  s_ha[NHA];
    __shared__ float2 s_tab[NTAB];
    __shared__ float  s_nvmn5;
    __shared__ int    s_b0;
    __shared__ unsigned int s_islast;
    __shared__ float  ws[8];
    const int tid  = threadIdx.x;
    const int lane = tid & 31;
    const int wid  = tid >> 5;

    // ---- prologue: every block rebuilds the table from g_hist ----
    if (tid == 0) {
        int mn = g_minneg;
        s_b0 = mn ? (4096 - mn) + ABS_OFF : 0x7FFFFFFF;
    }
    __syncthreads();

    unsigned int h0 = g_hist[4 * tid + 0], h1 = g_hist[4 * tid + 1];
    unsigned int h2 = g_hist[4 * tid + 2], h3 = g_hist[4 * tid + 3];
    if (h0 | h1 | h2 | h3)
        atomicMin(&s_b0, 4 * tid + (h0 ? 0 : h1 ? 1 : h2 ? 2 : 3));

    unsigned int p0 = h0, p1 = p0 + h1, p2 = p1 + h2, S = p2 + h3;
    unsigned int x = S;
    #pragma unroll
    for (int o = 1; o < 32; o <<= 1) {
        unsigned int y = __shfl_up_sync(0xFFFFFFFFu, x, o);
        if (lane >= o) x += y;
    }
    if (lane == 31) s_wsum[wid] = x;
    unsigned int excl = x - S;
    __syncthreads();
    if (tid == 0) {
        unsigned int a = 0;
        #pragma unroll
        for (int w = 0; w < 8; w++) { unsigned int t = s_wsum[w]; s_wsum[w] = a; a += t; }
    }
    __syncthreads();
    unsigned int boff = s_wsum[wid] + excl;
    s_cum[4 * tid + 0] = boff + p0;
    s_cum[4 * tid + 1] = boff + p1;
    s_cum[4 * tid + 2] = boff + p2;
    s_cum[4 * tid + 3] = boff + S;
    __syncthreads();

    const unsigned int total = s_cum[NBINS_ABS - 1];
    int b0rel = s_b0 - ABS_OFF;                 // floor(5 * xmin)
    int fd = (b0rel >= 0) ? (b0rel / 5) : -((-b0rel + 4) / 5);
    int vmin_i = fd - 1;
    int hbase = 5 * vmin_i + ABS_OFF;

    if (tid < NHA) {
        int j = tid;
        double lo, hi;
        if (j == 0) lo = 0.0;
        else {
            int k = hbase + j - 1;
            lo = (k < 0) ? 0.0 : (double)((k >= NBINS_ABS) ? total : s_cum[k]);
        }
        if (j >= NHA - 1) hi = (double)total;
        else {
            int k = hbase + j + 4;
            hi = (k < 0) ? 0.0 : (double)((k >= NBINS_ABS) ? total : s_cum[k]);
        }
        s_ha[j] = (float)((hi - lo) * inv_n);
    }
    __syncthreads();
    if (tid < NTAB) {
        float A = s_ha[tid + 1] - s_ha[tid];
        float B = (float)((double)s_ha[tid] + 1e-8 - (double)tid * (double)A);
        s_tab[tid] = make_float2(A, B);
    }
    if (tid == 0) s_nvmn5 = -(((float)vmin_i + 0.5f) * 5.0f);
    __syncthreads();

    const float nvmn5 = s_nvmn5;
    const float2* tab = s_tab;

    // ---- main loss loop: reverse traversal (L2 reuse from k_hist) ----
    const int n4 = n >> 2;
    const float4* p = (const float4*)xp + (n4 - 1);
    const int stride = gridDim.x * blockDim.x;

    float acc = 0.0f;
    for (int i = blockIdx.x * blockDim.x + tid; i < n4; i += 2 * stride) {
        float4 a = p[-i];
        int ea; float ma;
        prod4(a, nvmn5, tab, ea, ma);
        int j = i + stride;
        if (j < n4) {
            float4 b = p[-j];
            int eb; float mb;
            prod4(b, nvmn5, tab, eb, mb);
            acc += (float)(ea + eb) + __log2f(ma * mb);
        } else {
            acc += (float)ea + __log2f(ma);
        }
    }
    if (blockIdx.x == 0 && tid < (n & 3)) {
        float f = xp[(n & ~3) + tid];
        acc += __log2f(nloss_of(f, nvmn5, tab));
    }

    // ---- reduce ----
    #pragma unroll
    for (int o = 16; o; o >>= 1) acc += __shfl_xor_sync(0xFFFFFFFFu, acc, o);
    if (lane == 0) ws[wid] = acc;
    __syncthreads();
    if (tid < 32) {
        float a2 = (tid < 8) ? ws[tid] : 0.0f;
        #pragma unroll
        for (int o = 4; o; o >>= 1) a2 += __shfl_xor_sync(0xFFFFFFFFu, a2, o);
        if (tid == 0) atomicAdd(&g_acc, (double)a2);
    }

    // ---- ticket: last block finalizes + resets all replay state ----
    if (tid == 0) {
        __threadfence();
        s_islast = (atomicInc(&g_tick, gridDim.x - 1) == gridDim.x - 1);
    }
    __syncthreads();
    if (s_islast) {
        for (int k = tid; k < NBINS_ABS; k += 256) g_hist[k] = 0u;
        if (tid == 0) {
            g_minneg = 0;
            double a3 = g_acc;
            g_acc = 0.0;
            out[0] = (float)(-a3 * inv_n);
        }
    }
}

// ---------------------------------------------------------------- launch
extern "C" void kernel_launch(void* const* d_in, const int* in_sizes, int n_in,
                              void* d_out, int out_size) {
    const float* x = (const float*)d_in[0];
    const int n = in_sizes[0];
    const double inv_n = 1.0 / (double)n;

    k_hist<<<GRID_N, 256>>>(x, n);
    k_loss<<<GRID_N, 256>>>(x, n, inv_n, (float*)d_out);
}

// round 10
// speedup vs baseline: 2.6256x; 1.1062x over previous
#include <cuda_runtime.h>

#define NBINS_ABS 1024
#define ABS_OFF   512
#define NTAB      195
#define NHA       196
#define LBINS     64                 // local bins: floor(5x) in [-32,31]
#define LBASE     (ABS_OFF - 32)
#define MAGIC_F   8388640.0f         // 2^23 + 32
#define MAGIC_U   0x4B000000u        // bits(2^23)
#define GRID_N    1184               // 148 SMs * 8

__device__ unsigned int g_hist[NBINS_ABS];
__device__ int          g_minneg;    // max over outliers of (4096 - floor(5x)); 0 = none
__device__ double       g_acc;
__device__ float2       g_table[NTAB];   // (A, B): nloss = t*A + B
__device__ float        g_nvmn5;         // -(vmin+0.5)*5
__device__ unsigned int g_tick1;
__device__ unsigned int g_tick2;

struct f8 { float4 a, b; };

// ---------------------------------------------------------------- 32B L2-persist load
static __device__ __forceinline__ f8 ldg_el8(const float* p) {
    f8 v;
    asm("ld.global.nc.L2::evict_last.v8.b32 {%0,%1,%2,%3,%4,%5,%6,%7}, [%8];"
        : "=f"(v.a.x), "=f"(v.a.y), "=f"(v.a.z), "=f"(v.a.w),
          "=f"(v.b.x), "=f"(v.b.y), "=f"(v.b.z), "=f"(v.b.w)
        : "l"(p));
    return v;
}

// ---------------------------------------------------------------- slow path
static __device__ __noinline__ void hbin_slow(float f) {
    int b = __float2int_rd(f * 5.0f);
    atomicAdd(&g_hist[min(NBINS_ABS - 1, max(0, b + ABS_OFF))], 1u);
    atomicMax(&g_minneg, 4096 - b);
}

// conflict-free per-thread byte counter: thread owns word (l>>2)*256+tid, byte (l&3).
// byte addr = ((u&0xFC)<<8) + (u&3) + (tid<<2);  bank = tid&31 always.
static __device__ __forceinline__ unsigned int haddr(unsigned int u, int tq) {
    return ((u & 0xFCu) << 8) + (u & 3u) + (unsigned int)tq;
}

static __device__ __forceinline__ void hq(const float4& a, unsigned char* sh8, int tq) {
    unsigned int u0 = __float_as_uint(__fmaf_rd(a.x, 5.0f, MAGIC_F));
    unsigned int u1 = __float_as_uint(__fmaf_rd(a.y, 5.0f, MAGIC_F));
    unsigned int u2 = __float_as_uint(__fmaf_rd(a.z, 5.0f, MAGIC_F));
    unsigned int u3 = __float_as_uint(__fmaf_rd(a.w, 5.0f, MAGIC_F));
    unsigned int l0 = u0 - MAGIC_U, l1 = u1 - MAGIC_U,
                 l2 = u2 - MAGIC_U, l3 = u3 - MAGIC_U;
    if ((l0 | l1 | l2 | l3) < LBINS) {
        sh8[haddr(u0, tq)]++;
        sh8[haddr(u1, tq)]++;
        sh8[haddr(u2, tq)]++;
        sh8[haddr(u3, tq)]++;
    } else {
        if (l0 < LBINS) sh8[haddr(u0, tq)]++; else hbin_slow(a.x);
        if (l1 < LBINS) sh8[haddr(u1, tq)]++; else hbin_slow(a.y);
        if (l2 < LBINS) sh8[haddr(u2, tq)]++; else hbin_slow(a.z);
        if (l3 < LBINS) sh8[haddr(u3, tq)]++; else hbin_slow(a.w);
    }
}

// ---------------------------------------------------------------- pass 1: histogram + last-block table build
__global__ void __launch_bounds__(256, 8) k_hist(const float* __restrict__ xp, int n, double inv_n) {
    __shared__ unsigned char sh8[16 * 1024];     // 16 rows x 256 words x 4 bins
    const int tid  = threadIdx.x;
    const int lane = tid & 31;
    const int wid  = tid >> 5;
    const int tq   = tid << 2;

    #pragma unroll
    for (int i = 0; i < 16; i++)
        ((unsigned int*)sh8)[i * 256 + tid] = 0u;
    __syncthreads();

    const int n8 = n >> 3;                       // 32-byte chunks
    const int stride = gridDim.x * blockDim.x;

    for (int i = blockIdx.x * blockDim.x + tid; i < n8; i += stride) {
        f8 v = ldg_el8(xp + 8 * (long long)i);
        hq(v.a, sh8, tq);
        hq(v.b, sh8, tq);
    }
    if (blockIdx.x == 0 && tid < (n & 7)) hbin_slow(xp[(n & ~7) + tid]);
    __syncthreads();

    // merge: row r holds bins 4r..4r+3; per-byte extraction via dp4a
    for (int r = wid; r < 16; r += 8) {
        const unsigned int* row = (const unsigned int*)sh8 + r * 256;
        unsigned int a0 = 0, a1 = 0, a2 = 0, a3 = 0;
        #pragma unroll
        for (int j = 0; j < 8; j++) {
            unsigned int w = row[lane + 32 * j];
            a0 = __dp4a(w, 0x00000001u, a0);
            a1 = __dp4a(w, 0x00000100u, a1);
            a2 = __dp4a(w, 0x00010000u, a2);
            a3 = __dp4a(w, 0x01000000u, a3);
        }
        #pragma unroll
        for (int o = 16; o; o >>= 1) {
            a0 += __shfl_xor_sync(0xFFFFFFFFu, a0, o);
            a1 += __shfl_xor_sync(0xFFFFFFFFu, a1, o);
            a2 += __shfl_xor_sync(0xFFFFFFFFu, a2, o);
            a3 += __shfl_xor_sync(0xFFFFFFFFu, a3, o);
        }
        if (lane == 0) {
            int b = LBASE + 4 * r;
            if (a0) atomicAdd(&g_hist[b + 0], a0);
            if (a1) atomicAdd(&g_hist[b + 1], a1);
            if (a2) atomicAdd(&g_hist[b + 2], a2);
            if (a3) atomicAdd(&g_hist[b + 3], a3);
        }
    }

    // ---- ticket: last block builds the tables ----
    __shared__ unsigned int s_islast;
    if (tid == 0) {
        __threadfence();
        s_islast = (atomicInc(&g_tick1, gridDim.x - 1) == gridDim.x - 1);
    }
    __syncthreads();
    if (!s_islast) return;

    __shared__ unsigned int s_cum[NBINS_ABS];
    __shared__ unsigned int s_wsum[8];
    __shared__ float s_ha[NHA];
    __shared__ int s_b0;
    if (tid == 0) {
        int mn = g_minneg; g_minneg = 0;
        s_b0 = mn ? (4096 - mn) + ABS_OFF : 0x7FFFFFFF;
    }
    __syncthreads();

    unsigned int h0 = g_hist[4 * tid + 0], h1 = g_hist[4 * tid + 1];
    unsigned int h2 = g_hist[4 * tid + 2], h3 = g_hist[4 * tid + 3];
    g_hist[4 * tid + 0] = 0u; g_hist[4 * tid + 1] = 0u;   // reset for replay
    g_hist[4 * tid + 2] = 0u; g_hist[4 * tid + 3] = 0u;
    if (h0 | h1 | h2 | h3)
        atomicMin(&s_b0, 4 * tid + (h0 ? 0 : h1 ? 1 : h2 ? 2 : 3));

    unsigned int p0 = h0, p1 = p0 + h1, p2 = p1 + h2, S = p2 + h3;
    unsigned int x = S;
    #pragma unroll
    for (int o = 1; o < 32; o <<= 1) {
        unsigned int y = __shfl_up_sync(0xFFFFFFFFu, x, o);
        if (lane >= o) x += y;
    }
    if (lane == 31) s_wsum[wid] = x;
    unsigned int excl = x - S;
    __syncthreads();
    if (tid == 0) {
        unsigned int a = 0;
        #pragma unroll
        for (int w = 0; w < 8; w++) { unsigned int t = s_wsum[w]; s_wsum[w] = a; a += t; }
    }
    __syncthreads();
    unsigned int boff = s_wsum[wid] + excl;
    s_cum[4 * tid + 0] = boff + p0;
    s_cum[4 * tid + 1] = boff + p1;
    s_cum[4 * tid + 2] = boff + p2;
    s_cum[4 * tid + 3] = boff + S;
    __syncthreads();

    const unsigned int total = s_cum[NBINS_ABS - 1];
    int b0rel = s_b0 - ABS_OFF;                 // floor(5 * xmin)
    int fd = (b0rel >= 0) ? (b0rel / 5) : -((-b0rel + 4) / 5);
    int vmin_i = fd - 1;
    int hbase = 5 * vmin_i + ABS_OFF;

    if (tid < NHA) {
        int j = tid;
        double lo, hi;
        if (j == 0) lo = 0.0;
        else {
            int k = hbase + j - 1;
            lo = (k < 0) ? 0.0 : (double)((k >= NBINS_ABS) ? total : s_cum[k]);
        }
        if (j >= NHA - 1) hi = (double)total;
        else {
            int k = hbase + j + 4;
            hi = (k < 0) ? 0.0 : (double)((k >= NBINS_ABS) ? total : s_cum[k]);
        }
        s_ha[j] = (float)((hi - lo) * inv_n);
    }
    __syncthreads();
    if (tid < NTAB) {
        float A = s_ha[tid + 1] - s_ha[tid];
        float B = (float)((double)s_ha[tid] + 1e-8 - (double)tid * (double)A);
        g_table[tid] = make_float2(A, B);
    }
    if (tid == 0) g_nvmn5 = -(((float)vmin_i + 0.5f) * 5.0f);
}

// ---------------------------------------------------------------- pass 2: lean loss
static __device__ __forceinline__ float nloss_of(float xv, float nvmn5, const float2* tab) {
    float t = fmaf(xv, 5.0f, nvmn5);     // >= 2.5 since x >= min
    int i = min(__float2int_rd(t), NTAB - 1);
    float2 ab = tab[i];
    return fmaf(t, ab.x, ab.y);
}

static __device__ __forceinline__ void prod4(const float4& v, float nvmn5,
                                             const float2* tab, int& e, float& m) {
    float p = nloss_of(v.x, nvmn5, tab) * nloss_of(v.y, nvmn5, tab)
            * nloss_of(v.z, nvmn5, tab) * nloss_of(v.w, nvmn5, tab);
    unsigned int ub = __float_as_uint(p);
    e = (int)(ub >> 23) - 127;
    m = __uint_as_float((ub & 0x007FFFFFu) | 0x3F800000u);
}

__global__ void __launch_bounds__(256, 8) k_loss(const float* __restrict__ xp, int n,
                                                 double inv_n, float* __restrict__ out) {
    __shared__ float2 tab[NTAB];
    for (int i = threadIdx.x; i < NTAB; i += blockDim.x) tab[i] = g_table[i];
    __syncthreads();
    const float nvmn5 = g_nvmn5;

    const int n8 = n >> 3;
    const int tid = blockIdx.x * blockDim.x + threadIdx.x;
    const int stride = gridDim.x * blockDim.x;

    float acc = 0.0f;
    // reverse traversal: consume what k_hist left most-recently in L2
    for (int i = tid; i < n8; i += stride) {
        f8 v = ldg_el8(xp + 8 * (long long)(n8 - 1 - i));
        int ea, eb; float ma, mb;
        prod4(v.a, nvmn5, tab, ea, ma);
        prod4(v.b, nvmn5, tab, eb, mb);
        acc += (float)(ea + eb) + __log2f(ma * mb);
    }
    if (blockIdx.x == 0 && threadIdx.x < (n & 7)) {
        float f = xp[(n & ~7) + threadIdx.x];
        acc += __log2f(nloss_of(f, nvmn5, tab));
    }

    #pragma unroll
    for (int o = 16; o; o >>= 1) acc += __shfl_xor_sync(0xFFFFFFFFu, acc, o);
    __shared__ float ws[8];
    if ((threadIdx.x & 31) == 0) ws[threadIdx.x >> 5] = acc;
    __syncthreads();
    if (threadIdx.x < 32) {
        float a = (threadIdx.x < 8) ? ws[threadIdx.x] : 0.0f;
        #pragma unroll
        for (int o = 4; o; o >>= 1) a += __shfl_xor_sync(0xFFFFFFFFu, a, o);
        if (threadIdx.x == 0) atomicAdd(&g_acc, (double)a);
    }

    // ---- ticket: last block finalizes ----
    if (threadIdx.x == 0) {
        __threadfence();
        if (atomicInc(&g_tick2, gridDim.x - 1) == gridDim.x - 1) {
            double a = g_acc;
            g_acc = 0.0;
            out[0] = (float)(-a * inv_n);
        }
    }
}

// ---------------------------------------------------------------- launch
extern "C" void kernel_launch(void* const* d_in, const int* in_sizes, int n_in,
                              void* d_out, int out_size) {
    const float* x = (const float*)d_in[0];
    const int n = in_sizes[0];
    const double inv_n = 1.0 / (double)n;

    k_hist<<<GRID_N, 256>>>(x, n, inv_n);
    k_loss<<<GRID_N, 256>>>(x, n, inv_n, (float*)d_out);
}

// round 11
// speedup vs baseline: 2.6490x; 1.0089x over previous
#include <cuda_runtime.h>

#define NBINS_ABS 1024
#define ABS_OFF   512
#define NTAB      195
#define NHA       196
#define LBINS     64                 // local bins: floor(5x) in [-32,31]
#define LBASE     (ABS_OFF - 32)
#define MAGIC_F   8388640.0f         // 2^23 + 32
#define MAGIC_U   0x4B000000u        // bits(2^23)
#define GRID_N    1184               // 148 SMs * 8

__device__ unsigned int g_hist[NBINS_ABS];
__device__ int          g_minneg;    // max over outliers of (4096 - floor(5x)); 0 = none
__device__ double       g_acc;
__device__ float2       g_table[NTAB];   // (A, B): nloss = t*A + B
__device__ float        g_nvmn5;         // -(vmin+0.5)*5
__device__ unsigned int g_tick1;
__device__ unsigned int g_tick2;

struct f8 { float4 a, b; };

// ---------------------------------------------------------------- 32B load (evict_last legal on v8)
static __device__ __forceinline__ f8 ldg_el8(const float* p) {
    f8 v;
    asm("ld.global.nc.L2::evict_last.v8.b32 {%0,%1,%2,%3,%4,%5,%6,%7}, [%8];"
        : "=f"(v.a.x), "=f"(v.a.y), "=f"(v.a.z), "=f"(v.a.w),
          "=f"(v.b.x), "=f"(v.b.y), "=f"(v.b.z), "=f"(v.b.w)
        : "l"(p));
    return v;
}

// ---------------------------------------------------------------- slow path
static __device__ __noinline__ void hbin_slow(float f) {
    int b = __float2int_rd(f * 5.0f);
    atomicAdd(&g_hist[min(NBINS_ABS - 1, max(0, b + ABS_OFF))], 1u);
    atomicMax(&g_minneg, 4096 - b);
}

// conflict-free per-thread byte counter: thread owns word (l>>2)*256+tid, byte (l&3).
// addr = ((u&0xFC)<<8) | (u&3) | (tid<<2)   -- all bit-disjoint;  bank = tid&31 always.
static __device__ __forceinline__ unsigned int haddr(unsigned int u, int tq) {
    return ((u & 0xFCu) << 8) | ((u & 3u) | (unsigned int)tq);
}

static __device__ __forceinline__ void hq(const float4& a, unsigned char* sh8, int tq) {
    unsigned int u0 = __float_as_uint(__fmaf_rd(a.x, 5.0f, MAGIC_F));
    unsigned int u1 = __float_as_uint(__fmaf_rd(a.y, 5.0f, MAGIC_F));
    unsigned int u2 = __float_as_uint(__fmaf_rd(a.z, 5.0f, MAGIC_F));
    unsigned int u3 = __float_as_uint(__fmaf_rd(a.w, 5.0f, MAGIC_F));
    // all-in-range <=> OR of the four stays inside [MAGIC_U, MAGIC_U+63]
    if (((u0 | u1 | u2 | u3) - MAGIC_U) < (unsigned int)LBINS) {
        sh8[haddr(u0, tq)]++;
        sh8[haddr(u1, tq)]++;
        sh8[haddr(u2, tq)]++;
        sh8[haddr(u3, tq)]++;
    } else {
        if (u0 - MAGIC_U < LBINS) sh8[haddr(u0, tq)]++; else hbin_slow(a.x);
        if (u1 - MAGIC_U < LBINS) sh8[haddr(u1, tq)]++; else hbin_slow(a.y);
        if (u2 - MAGIC_U < LBINS) sh8[haddr(u2, tq)]++; else hbin_slow(a.z);
        if (u3 - MAGIC_U < LBINS) sh8[haddr(u3, tq)]++; else hbin_slow(a.w);
    }
}

// ---------------------------------------------------------------- pass 1: histogram + last-block table build
__global__ void __launch_bounds__(256, 8) k_hist(const float* __restrict__ xp, int n, double inv_n) {
    __shared__ unsigned char sh8[16 * 1024];     // 16 rows x 256 words x 4 bins
    const int tid  = threadIdx.x;
    const int lane = tid & 31;
    const int wid  = tid >> 5;
    const int tq   = tid << 2;

    #pragma unroll
    for (int i = 0; i < 16; i++)
        ((unsigned int*)sh8)[i * 256 + tid] = 0u;
    __syncthreads();

    const int n8 = n >> 3;
    const int stride = gridDim.x * blockDim.x;

    for (int i = blockIdx.x * blockDim.x + tid; i < n8; i += stride) {
        f8 v = ldg_el8(xp + 8 * (long long)i);
        hq(v.a, sh8, tq);
        hq(v.b, sh8, tq);
    }
    if (blockIdx.x == 0 && tid < (n & 7)) hbin_slow(xp[(n & ~7) + tid]);
    __syncthreads();

    // merge: row r holds bins 4r..4r+3; per-byte extraction via dp4a
    for (int r = wid; r < 16; r += 8) {
        const unsigned int* row = (const unsigned int*)sh8 + r * 256;
        unsigned int a0 = 0, a1 = 0, a2 = 0, a3 = 0;
        #pragma unroll
        for (int j = 0; j < 8; j++) {
            unsigned int w = row[lane + 32 * j];
            a0 = __dp4a(w, 0x00000001u, a0);
            a1 = __dp4a(w, 0x00000100u, a1);
            a2 = __dp4a(w, 0x00010000u, a2);
            a3 = __dp4a(w, 0x01000000u, a3);
        }
        #pragma unroll
        for (int o = 16; o; o >>= 1) {
            a0 += __shfl_xor_sync(0xFFFFFFFFu, a0, o);
            a1 += __shfl_xor_sync(0xFFFFFFFFu, a1, o);
            a2 += __shfl_xor_sync(0xFFFFFFFFu, a2, o);
            a3 += __shfl_xor_sync(0xFFFFFFFFu, a3, o);
        }
        if (lane == 0) {
            int b = LBASE + 4 * r;
            if (a0) atomicAdd(&g_hist[b + 0], a0);
            if (a1) atomicAdd(&g_hist[b + 1], a1);
            if (a2) atomicAdd(&g_hist[b + 2], a2);
            if (a3) atomicAdd(&g_hist[b + 3], a3);
        }
    }

    // ---- ticket: last block builds the tables ----
    __shared__ unsigned int s_islast;
    if (tid == 0) {
        __threadfence();
        s_islast = (atomicInc(&g_tick1, gridDim.x - 1) == gridDim.x - 1);
    }
    __syncthreads();
    if (!s_islast) return;

    __shared__ unsigned int s_cum[NBINS_ABS];
    __shared__ unsigned int s_wsum[8];
    __shared__ float s_ha[NHA];
    __shared__ int s_b0;
    if (tid == 0) {
        int mn = g_minneg; g_minneg = 0;
        s_b0 = mn ? (4096 - mn) + ABS_OFF : 0x7FFFFFFF;
    }
    __syncthreads();

    unsigned int h0 = g_hist[4 * tid + 0], h1 = g_hist[4 * tid + 1];
    unsigned int h2 = g_hist[4 * tid + 2], h3 = g_hist[4 * tid + 3];
    g_hist[4 * tid + 0] = 0u; g_hist[4 * tid + 1] = 0u;   // reset for replay
    g_hist[4 * tid + 2] = 0u; g_hist[4 * tid + 3] = 0u;
    if (h0 | h1 | h2 | h3)
        atomicMin(&s_b0, 4 * tid + (h0 ? 0 : h1 ? 1 : h2 ? 2 : 3));

    unsigned int p0 = h0, p1 = p0 + h1, p2 = p1 + h2, S = p2 + h3;
    unsigned int x = S;
    #pragma unroll
    for (int o = 1; o < 32; o <<= 1) {
        unsigned int y = __shfl_up_sync(0xFFFFFFFFu, x, o);
        if (lane >= o) x += y;
    }
    if (lane == 31) s_wsum[wid] = x;
    unsigned int excl = x - S;
    __syncthreads();
    if (tid == 0) {
        unsigned int a = 0;
        #pragma unroll
        for (int w = 0; w < 8; w++) { unsigned int t = s_wsum[w]; s_wsum[w] = a; a += t; }
    }
    __syncthreads();
    unsigned int boff = s_wsum[wid] + excl;
    s_cum[4 * tid + 0] = boff + p0;
    s_cum[4 * tid + 1] = boff + p1;
    s_cum[4 * tid + 2] = boff + p2;
    s_cum[4 * tid + 3] = boff + S;
    __syncthreads();

    const unsigned int total = s_cum[NBINS_ABS - 1];
    int b0rel = s_b0 - ABS_OFF;                 // floor(5 * xmin)
    int fd = (b0rel >= 0) ? (b0rel / 5) : -((-b0rel + 4) / 5);
    int vmin_i = fd - 1;
    int hbase = 5 * vmin_i + ABS_OFF;

    if (tid < NHA) {
        int j = tid;
        double lo, hi;
        if (j == 0) lo = 0.0;
        else {
            int k = hbase + j - 1;
            lo = (k < 0) ? 0.0 : (double)((k >= NBINS_ABS) ? total : s_cum[k]);
        }
        if (j >= NHA - 1) hi = (double)total;
        else {
            int k = hbase + j + 4;
            hi = (k < 0) ? 0.0 : (double)((k >= NBINS_ABS) ? total : s_cum[k]);
        }
        s_ha[j] = (float)((hi - lo) * inv_n);
    }
    __syncthreads();
    if (tid < NTAB) {
        float A = s_ha[tid + 1] - s_ha[tid];
        float B = (float)((double)s_ha[tid] + 1e-8 - (double)tid * (double)A);
        g_table[tid] = make_float2(A, B);
    }
    if (tid == 0) g_nvmn5 = -(((float)vmin_i + 0.5f) * 5.0f);
}

// ---------------------------------------------------------------- pass 2: lean loss
static __device__ __forceinline__ float nloss_of(float xv, float nvmn5, const float2* tab) {
    float t = fmaf(xv, 5.0f, nvmn5);     // >= 2.5 since x >= min
    int i = min(__float2int_rd(t), NTAB - 1);
    float2 ab = tab[i];
    return fmaf(t, ab.x, ab.y);
}

// product of 4 nloss: raw biased exponent (no -127), mantissa in [1,2)
static __device__ __forceinline__ void prod4r(const float4& v, float nvmn5,
                                              const float2* tab, unsigned int& eraw, float& m) {
    float p = nloss_of(v.x, nvmn5, tab) * nloss_of(v.y, nvmn5, tab)
            * nloss_of(v.z, nvmn5, tab) * nloss_of(v.w, nvmn5, tab);
    unsigned int ub = __float_as_uint(p);
    eraw = ub >> 23;
    m = __uint_as_float((ub & 0x007FFFFFu) | 0x3F800000u);
}

__global__ void __launch_bounds__(256, 8) k_loss(const float* __restrict__ xp, int n,
                                                 double inv_n, float* __restrict__ out) {
    __shared__ float2 tab[NTAB];
    for (int i = threadIdx.x; i < NTAB; i += blockDim.x) tab[i] = g_table[i];
    __syncthreads();
    const float nvmn5 = g_nvmn5;

    const int n8 = n >> 3;
    const int tid = blockIdx.x * blockDim.x + threadIdx.x;
    const int stride = gridDim.x * blockDim.x;

    float acc = 0.0f;          // sum of log2(mantissa products)
    unsigned int acc_e = 0u;   // sum of raw biased exponents (2 per iter)
    int cnt = 0;
    for (int i = tid; i < n8; i += stride) {
        f8 v = ldg_el8(xp + 8 * (long long)(n8 - 1 - i));
        unsigned int ea, eb; float ma, mb;
        prod4r(v.a, nvmn5, tab, ea, ma);
        prod4r(v.b, nvmn5, tab, eb, mb);
        acc_e += ea + eb;
        acc += __log2f(ma * mb);
        cnt++;
    }
    // fold deferred bias: each iter contributed 2 exponents, each biased by +127
    acc += (float)((int)acc_e - 254 * cnt);

    if (blockIdx.x == 0 && threadIdx.x < (n & 7)) {
        float f = xp[(n & ~7) + threadIdx.x];
        acc += __log2f(nloss_of(f, nvmn5, tab));
    }

    #pragma unroll
    for (int o = 16; o; o >>= 1) acc += __shfl_xor_sync(0xFFFFFFFFu, acc, o);
    __shared__ float ws[8];
    if ((threadIdx.x & 31) == 0) ws[threadIdx.x >> 5] = acc;
    __syncthreads();
    if (threadIdx.x < 32) {
        float a = (threadIdx.x < 8) ? ws[threadIdx.x] : 0.0f;
        #pragma unroll
        for (int o = 4; o; o >>= 1) a += __shfl_xor_sync(0xFFFFFFFFu, a, o);
        if (threadIdx.x == 0) atomicAdd(&g_acc, (double)a);
    }

    // ---- ticket: last block finalizes ----
    if (threadIdx.x == 0) {
        __threadfence();
        if (atomicInc(&g_tick2, gridDim.x - 1) == gridDim.x - 1) {
            double a = g_acc;
            g_acc = 0.0;
            out[0] = (float)(-a * inv_n);
        }
    }
}

// ---------------------------------------------------------------- launch
extern "C" void kernel_launch(void* const* d_in, const int* in_sizes, int n_in,
                              void* d_out, int out_size) {
    const float* x = (const float*)d_in[0];
    const int n = in_sizes[0];
    const double inv_n = 1.0 / (double)n;

    k_hist<<<GRID_N, 256>>>(x, n, inv_n);
    k_loss<<<GRID_N, 256>>>(x, n, inv_n, (float*)d_out);
}